// round 3
// baseline (speedup 1.0000x reference)
#include <cuda_runtime.h>
#include <math.h>
#include <stdint.h>

#define NP 100000
#define NA 50000
#define EMAX 500000
#define DMODEL 128
#define NH 8
#define HDIM 16

// ---------------- scratch (device globals; no allocation allowed) ----------------
__device__ float g_Wk_ap[DMODEL * DMODEL];
__device__ float g_Wv_ap[DMODEL * DMODEL];
__device__ float g_Wk_pa[DMODEL * DMODEL];
__device__ float g_Wv_pa[DMODEL * DMODEL];
__device__ float g_bk_ap[DMODEL];
__device__ float g_bv_ap[DMODEL];
__device__ float g_bk_pa[DMODEL];
__device__ float g_bv_pa[DMODEL];

__device__ float g_q_p[(size_t)NP * DMODEL];
__device__ float g_k_pa[(size_t)NP * DMODEL];
__device__ float g_v_pa[(size_t)NP * DMODEL];
__device__ float g_q_a[(size_t)NA * DMODEL];
__device__ float g_k_ap[(size_t)NA * DMODEL];
__device__ float g_v_ap[(size_t)NA * DMODEL];

// CSR-by-dst machinery
__device__ int g_cnt_p[NP];
__device__ int g_cnt_a[NA];
__device__ int g_off_p[NP + 1];
__device__ int g_off_a[NA + 1];
__device__ int g_cur_p[NP];
__device__ int g_cur_a[NA];
__device__ int g_esrc_p[EMAX];
__device__ int g_esrc_a[EMAX];
__device__ float g_eev_p[(size_t)EMAX * NH];
__device__ float g_eev_a[(size_t)EMAX * NH];

__device__ float g_agg_p[(size_t)NP * DMODEL];
__device__ float g_agg_a[(size_t)NA * DMODEL];

// ---------------- packed f32x2 helpers (FFMA2) ----------------
__device__ __forceinline__ void fma2(unsigned long long& c,
                                     unsigned long long a, unsigned long long b) {
    asm("fma.rn.f32x2 %0, %1, %2, %0;" : "+l"(c) : "l"(a), "l"(b));
}
__device__ __forceinline__ unsigned long long dup2(float x) {
    unsigned long long r;
    unsigned int xb = __float_as_uint(x);
    asm("mov.b64 %0, {%1, %1};" : "=l"(r) : "r"(xb));
    return r;
}
__device__ __forceinline__ float lo32(unsigned long long v) {
    return __uint_as_float((unsigned int)v);
}
__device__ __forceinline__ float hi32(unsigned long long v) {
    return __uint_as_float((unsigned int)(v >> 32));
}

// ---------------- setup kernels ----------------
struct FuseArgs {
    const float* W[4];
    const float* b[4];
    const float* rel[4];
    float* We[4];
    float* be[4];
};

// Weff[k, h*16+e] = sum_d W[k, h*16+d] * rel[h, d, e]; beff analogous. 4 sets in one launch.
__global__ void fuse_all(FuseArgs a) {
    int m = blockIdx.y;
    int k = blockIdx.x;
    int tid = threadIdx.x;
    int h = tid >> 4;
    int e = tid & 15;
    const float* r = a.rel[m] + h * HDIM * HDIM;
    const float* wrow = a.W[m] + k * DMODEL + h * HDIM;
    float s = 0.0f;
#pragma unroll
    for (int d = 0; d < HDIM; d++) s += wrow[d] * r[d * HDIM + e];
    a.We[m][k * DMODEL + tid] = s;
    if (k == 0) {
        const float* bb = a.b[m] + h * HDIM;
        float sb = 0.0f;
#pragma unroll
        for (int d = 0; d < HDIM; d++) sb += bb[d] * r[d * HDIM + e];
        a.be[m][tid] = sb;
    }
}

__global__ void fill_cnt(int* __restrict__ c0, int n0, int* __restrict__ c1, int n1) {
    int i = blockIdx.x * blockDim.x + threadIdx.x;
    int stride = gridDim.x * blockDim.x;
    for (; i < n0 + n1; i += stride) {
        if (i < n0) c0[i] = 0;
        else c1[i - n0] = 0;
    }
}

__global__ void hist2(const int* __restrict__ d0, int E0, int* __restrict__ c0,
                      const int* __restrict__ d1, int E1, int* __restrict__ c1) {
    int i = blockIdx.x * blockDim.x + threadIdx.x;
    int stride = gridDim.x * blockDim.x;
    for (; i < E0 + E1; i += stride) {
        if (i < E0) atomicAdd(&c0[d0[i]], 1);
        else atomicAdd(&c1[d1[i - E0]], 1);
    }
}

// single-block exclusive scan of two arrays -> off (n+1 entries) and cur (copy)
__device__ void scan_one(const int* __restrict__ cnt, int n,
                         int* __restrict__ off, int* __restrict__ cur,
                         int* warp_sums) {
    int tid = threadIdx.x;
    int lane = tid & 31;
    int wid = tid >> 5;
    int base = 0;
    for (int chunk = 0; chunk < n; chunk += 1024) {
        int i = chunk + tid;
        int v = (i < n) ? cnt[i] : 0;
        int x = v;
#pragma unroll
        for (int d = 1; d < 32; d <<= 1) {
            int t = __shfl_up_sync(0xffffffffu, x, d);
            if (lane >= d) x += t;
        }
        if (lane == 31) warp_sums[wid] = x;
        __syncthreads();
        if (wid == 0) {
            int s = warp_sums[lane];
#pragma unroll
            for (int d = 1; d < 32; d <<= 1) {
                int t = __shfl_up_sync(0xffffffffu, s, d);
                if (lane >= d) s += t;
            }
            warp_sums[lane] = s;
        }
        __syncthreads();
        int wbase = (wid == 0) ? 0 : warp_sums[wid - 1];
        int total = warp_sums[31];
        int excl = base + wbase + x - v;
        if (i < n) {
            off[i] = excl;
            cur[i] = excl;
        }
        __syncthreads();
        base += total;
    }
    if (tid == 0) off[n] = base;
}

__global__ __launch_bounds__(1024) void scan2(
        const int* cnt0, int n0, int* off0, int* cur0,
        const int* cnt1, int n1, int* off1, int* cur1) {
    __shared__ int warp_sums[32];
    scan_one(cnt0, n0, off0, cur0, warp_sums);
    __syncthreads();
    scan_one(cnt1, n1, off1, cur1, warp_sums);
}

// ---------------- shared-memory GEMM core: 128x128 tile, 8x8 per thread, FFMA2 ----------
__device__ __forceinline__ void mm_core(const float* __restrict__ Xs,
                                        const float* __restrict__ Ws,
                                        int rg, int c4,
                                        unsigned long long acc[8][4]) {
#pragma unroll
    for (int i = 0; i < 8; i++)
#pragma unroll
        for (int j = 0; j < 4; j++) acc[i][j] = 0ull;

#pragma unroll 4
    for (int k = 0; k < DMODEL; k++) {
        ulonglong2 wa = *(const ulonglong2*)&Ws[k * DMODEL + c4];
        ulonglong2 wb = *(const ulonglong2*)&Ws[k * DMODEL + c4 + 64];
#pragma unroll
        for (int i = 0; i < 8; i++) {
            unsigned long long x2 = dup2(Xs[(rg + i) * DMODEL + k]);
            fma2(acc[i][0], x2, wa.x);
            fma2(acc[i][1], x2, wa.y);
            fma2(acc[i][2], x2, wb.x);
            fma2(acc[i][3], x2, wb.y);
        }
    }
}

// ---------------- fused Q/K/V projection ----------------
__global__ __launch_bounds__(256) void gemm_qkv3(
        const float* __restrict__ X,
        const float* __restrict__ W0, const float* __restrict__ b0, float* __restrict__ Y0,
        const float* __restrict__ W1, const float* __restrict__ b1, float* __restrict__ Y1,
        const float* __restrict__ W2, const float* __restrict__ b2, float* __restrict__ Y2,
        int N) {
    extern __shared__ float sm[];
    float* Xs = sm;
    float* Ws = sm + DMODEL * DMODEL;
    int tid = threadIdx.x;
    int row0 = blockIdx.x * DMODEL;

    {
        const float4* Xg = (const float4*)X;
        float4* Xsv = (float4*)Xs;
#pragma unroll
        for (int i = tid; i < DMODEL * 32; i += 256) {
            int gr = row0 + (i >> 5);
            float4 v = make_float4(0.f, 0.f, 0.f, 0.f);
            if (gr < N) v = Xg[(size_t)gr * 32 + (i & 31)];
            Xsv[i] = v;
        }
    }

    int rg = (tid >> 4) * 8;
    int c4 = (tid & 15) * 4;
    const float* Wm[3] = {W0, W1, W2};
    const float* bm[3] = {b0, b1, b2};
    float* Ym[3] = {Y0, Y1, Y2};

#pragma unroll 1
    for (int m = 0; m < 3; m++) {
        {
            const float4* Wg = (const float4*)Wm[m];
            float4* Wsv = (float4*)Ws;
#pragma unroll
            for (int i = tid; i < DMODEL * 32; i += 256) Wsv[i] = Wg[i];
        }
        __syncthreads();

        unsigned long long acc[8][4];
        mm_core(Xs, Ws, rg, c4, acc);

        const float* bias = bm[m];
        float4 bv0 = *(const float4*)&bias[c4];
        float4 bv1 = *(const float4*)&bias[c4 + 64];
        float* Y = Ym[m];
#pragma unroll
        for (int i = 0; i < 8; i++) {
            int gr = row0 + rg + i;
            if (gr < N) {
                float4 o0, o1;
                o0.x = lo32(acc[i][0]) + bv0.x;
                o0.y = hi32(acc[i][0]) + bv0.y;
                o0.z = lo32(acc[i][1]) + bv0.z;
                o0.w = hi32(acc[i][1]) + bv0.w;
                o1.x = lo32(acc[i][2]) + bv1.x;
                o1.y = hi32(acc[i][2]) + bv1.y;
                o1.z = lo32(acc[i][3]) + bv1.z;
                o1.w = hi32(acc[i][3]) + bv1.w;
                *(float4*)&Y[(size_t)gr * DMODEL + c4] = o0;
                *(float4*)&Y[(size_t)gr * DMODEL + c4 + 64] = o1;
            }
        }
        __syncthreads();
    }
}

// ---------------- output GEMM: Y = al*(agg @ W + b) + (1-al)*Xres ----------------
__global__ __launch_bounds__(256) void gemm_out(
        const float* __restrict__ Xagg,
        const float* __restrict__ W, const float* __restrict__ bias,
        const float* __restrict__ skip, const float* __restrict__ Xres,
        float* __restrict__ Y, int N) {
    extern __shared__ float sm[];
    float* Xs = sm;
    float* Ws = sm + DMODEL * DMODEL;
    int tid = threadIdx.x;
    int row0 = blockIdx.x * DMODEL;

    {
        const float4* Xg = (const float4*)Xagg;
        float4* Xsv = (float4*)Xs;
#pragma unroll
        for (int i = tid; i < DMODEL * 32; i += 256) {
            int gr = row0 + (i >> 5);
            float4 v = make_float4(0.f, 0.f, 0.f, 0.f);
            if (gr < N) v = Xg[(size_t)gr * 32 + (i & 31)];
            Xsv[i] = v;
        }
        const float4* Wg = (const float4*)W;
        float4* Wsv = (float4*)Ws;
#pragma unroll
        for (int i = tid; i < DMODEL * 32; i += 256) Wsv[i] = Wg[i];
    }
    __syncthreads();

    int rg = (tid >> 4) * 8;
    int c4 = (tid & 15) * 4;
    unsigned long long acc[8][4];
    mm_core(Xs, Ws, rg, c4, acc);

    float al = 1.0f / (1.0f + __expf(-skip[0]));
    float be = 1.0f - al;
    float4 bv0 = *(const float4*)&bias[c4];
    float4 bv1 = *(const float4*)&bias[c4 + 64];
#pragma unroll
    for (int i = 0; i < 8; i++) {
        int gr = row0 + rg + i;
        if (gr < N) {
            float4 x0 = *(const float4*)&Xres[(size_t)gr * DMODEL + c4];
            float4 x1 = *(const float4*)&Xres[(size_t)gr * DMODEL + c4 + 64];
            float4 o0, o1;
            o0.x = al * (lo32(acc[i][0]) + bv0.x) + be * x0.x;
            o0.y = al * (hi32(acc[i][0]) + bv0.y) + be * x0.y;
            o0.z = al * (lo32(acc[i][1]) + bv0.z) + be * x0.z;
            o0.w = al * (hi32(acc[i][1]) + bv0.w) + be * x0.w;
            o1.x = al * (lo32(acc[i][2]) + bv1.x) + be * x1.x;
            o1.y = al * (hi32(acc[i][2]) + bv1.y) + be * x1.y;
            o1.z = al * (lo32(acc[i][3]) + bv1.z) + be * x1.z;
            o1.w = al * (hi32(acc[i][3]) + bv1.w) + be * x1.w;
            *(float4*)&Y[(size_t)gr * DMODEL + c4] = o0;
            *(float4*)&Y[(size_t)gr * DMODEL + c4 + 64] = o1;
        }
    }
}

// ---------------- edge pass C: logits -> ev, compacted by dst via cursor ----------------
// one warp per edge. No max-subtraction needed (softmax shift-invariance; logits O(10)).
__global__ void edge_logits_fill(const float* __restrict__ K, const float* __restrict__ Q,
                                 const int* __restrict__ src, const int* __restrict__ dst,
                                 const float* __restrict__ p_rel,
                                 int* __restrict__ cur,
                                 float* __restrict__ eev, int* __restrict__ esrc, int E) {
    int g = blockIdx.x * blockDim.x + threadIdx.x;
    int e = g >> 5;
    int lane = g & 31;
    if (e >= E) return;
    int s = src[e];
    int d = dst[e];
    float4 kv = ((const float4*)(K + (size_t)s * DMODEL))[lane];
    float4 qv = ((const float4*)(Q + (size_t)d * DMODEL))[lane];
    float p = kv.x * qv.x + kv.y * qv.y + kv.z * qv.z + kv.w * qv.w;
    p += __shfl_xor_sync(0xffffffffu, p, 1);
    p += __shfl_xor_sync(0xffffffffu, p, 2);
    int h = lane >> 2;
    float ev = __expf(p * __ldg(&p_rel[h]) * 0.25f);   // / sqrt(D=16)
    int pos = 0;
    if (lane == 0) pos = atomicAdd(&cur[d], 1);
    pos = __shfl_sync(0xffffffffu, pos, 0);
    // gather the 8 head values into lanes 0..7 and write one 32B record
    float evl = __shfl_sync(0xffffffffu, ev, (lane & 7) * 4);
    if (lane < 8) eev[(size_t)pos * NH + lane] = evl;
    else if (lane == 8) esrc[pos] = s;
}

// ---------------- edge pass D: per-dst gather-aggregate, normalized plain store ---------
// one warp per destination node.
__global__ void node_aggregate(const float* __restrict__ V,
                               const int* __restrict__ off, const int* __restrict__ esrc,
                               const float* __restrict__ eev,
                               float* __restrict__ agg, int N) {
    int g = blockIdx.x * blockDim.x + threadIdx.x;
    int w = g >> 5;
    int lane = g & 31;
    if (w >= N) return;
    int j0 = off[w];
    int j1 = off[w + 1];
    int h = lane >> 2;
    float4 acc = make_float4(0.f, 0.f, 0.f, 0.f);
    float den = 0.0f;
    for (int j = j0; j < j1; j++) {
        float ev = __ldg(&eev[(size_t)j * NH + h]);
        int s = __ldg(&esrc[j]);
        float4 v = ((const float4*)(V + (size_t)s * DMODEL))[lane];
        acc.x += ev * v.x;
        acc.y += ev * v.y;
        acc.z += ev * v.z;
        acc.w += ev * v.w;
        den += ev;
    }
    float inv = 1.0f / (den + 1e-16f);
    float4 o;
    o.x = acc.x * inv;
    o.y = acc.y * inv;
    o.z = acc.z * inv;
    o.w = acc.w * inv;
    ((float4*)(agg + (size_t)w * DMODEL))[lane] = o;
}

// ---------------- launch ----------------
extern "C" void kernel_launch(void* const* d_in, const int* in_sizes, int n_in,
                              void* d_out, int out_size) {
    const float* x_p = (const float*)d_in[0];
    const float* x_a = (const float*)d_in[1];
    const int* src_ap = (const int*)d_in[2];
    const int* dst_ap = (const int*)d_in[3];
    const int* src_pa = (const int*)d_in[4];
    const int* dst_pa = (const int*)d_in[5];
    const float* Wq_p = (const float*)d_in[6];
    const float* bq_p = (const float*)d_in[7];
    const float* Wk_p = (const float*)d_in[8];
    const float* bk_p = (const float*)d_in[9];
    const float* Wv_p = (const float*)d_in[10];
    const float* bv_p = (const float*)d_in[11];
    const float* Wa_p = (const float*)d_in[12];
    const float* ba_p = (const float*)d_in[13];
    const float* skip_p = (const float*)d_in[14];
    const float* Wq_a = (const float*)d_in[15];
    const float* bq_a = (const float*)d_in[16];
    const float* Wk_a = (const float*)d_in[17];
    const float* bk_a = (const float*)d_in[18];
    const float* Wv_a = (const float*)d_in[19];
    const float* bv_a = (const float*)d_in[20];
    const float* Wa_a = (const float*)d_in[21];
    const float* ba_a = (const float*)d_in[22];
    const float* skip_a = (const float*)d_in[23];
    const float* a_rel_ap = (const float*)d_in[24];
    const float* m_rel_ap = (const float*)d_in[25];
    const float* p_rel_ap = (const float*)d_in[26];
    const float* a_rel_pa = (const float*)d_in[27];
    const float* m_rel_pa = (const float*)d_in[28];
    const float* p_rel_pa = (const float*)d_in[29];
    float* out = (float*)d_out;

    int E_ap = in_sizes[2];
    int E_pa = in_sizes[4];

    float *Wk_ap, *Wv_ap, *Wk_pa, *Wv_pa, *bk_ap, *bv_ap, *bk_pa, *bv_pa;
    float *q_p, *k_pa, *v_pa, *q_a, *k_ap, *v_ap, *agg_p, *agg_a;
    float *eev_p, *eev_a;
    int *cnt_p, *cnt_a, *off_p, *off_a, *cur_p, *cur_a, *esrc_p, *esrc_a;
    cudaGetSymbolAddress((void**)&Wk_ap, g_Wk_ap);
    cudaGetSymbolAddress((void**)&Wv_ap, g_Wv_ap);
    cudaGetSymbolAddress((void**)&Wk_pa, g_Wk_pa);
    cudaGetSymbolAddress((void**)&Wv_pa, g_Wv_pa);
    cudaGetSymbolAddress((void**)&bk_ap, g_bk_ap);
    cudaGetSymbolAddress((void**)&bv_ap, g_bv_ap);
    cudaGetSymbolAddress((void**)&bk_pa, g_bk_pa);
    cudaGetSymbolAddress((void**)&bv_pa, g_bv_pa);
    cudaGetSymbolAddress((void**)&q_p, g_q_p);
    cudaGetSymbolAddress((void**)&k_pa, g_k_pa);
    cudaGetSymbolAddress((void**)&v_pa, g_v_pa);
    cudaGetSymbolAddress((void**)&q_a, g_q_a);
    cudaGetSymbolAddress((void**)&k_ap, g_k_ap);
    cudaGetSymbolAddress((void**)&v_ap, g_v_ap);
    cudaGetSymbolAddress((void**)&agg_p, g_agg_p);
    cudaGetSymbolAddress((void**)&agg_a, g_agg_a);
    cudaGetSymbolAddress((void**)&eev_p, g_eev_p);
    cudaGetSymbolAddress((void**)&eev_a, g_eev_a);
    cudaGetSymbolAddress((void**)&cnt_p, g_cnt_p);
    cudaGetSymbolAddress((void**)&cnt_a, g_cnt_a);
    cudaGetSymbolAddress((void**)&off_p, g_off_p);
    cudaGetSymbolAddress((void**)&off_a, g_off_a);
    cudaGetSymbolAddress((void**)&cur_p, g_cur_p);
    cudaGetSymbolAddress((void**)&cur_a, g_cur_a);
    cudaGetSymbolAddress((void**)&esrc_p, g_esrc_p);
    cudaGetSymbolAddress((void**)&esrc_a, g_esrc_a);

    const int SMEM = 2 * DMODEL * DMODEL * (int)sizeof(float);  // 128 KB
    cudaFuncSetAttribute(gemm_qkv3, cudaFuncAttributeMaxDynamicSharedMemorySize, SMEM);
    cudaFuncSetAttribute(gemm_out, cudaFuncAttributeMaxDynamicSharedMemorySize, SMEM);

    // launch 0: fold relation matrices into projection weights (all 4 sets)
    FuseArgs fa;
    fa.W[0] = Wk_a; fa.b[0] = bk_a; fa.rel[0] = a_rel_ap; fa.We[0] = Wk_ap; fa.be[0] = bk_ap;
    fa.W[1] = Wv_a; fa.b[1] = bv_a; fa.rel[1] = m_rel_ap; fa.We[1] = Wv_ap; fa.be[1] = bv_ap;
    fa.W[2] = Wk_p; fa.b[2] = bk_p; fa.rel[2] = a_rel_pa; fa.We[2] = Wk_pa; fa.be[2] = bk_pa;
    fa.W[3] = Wv_p; fa.b[3] = bv_p; fa.rel[3] = m_rel_pa; fa.We[3] = Wv_pa; fa.be[3] = bv_pa;
    fuse_all<<<dim3(DMODEL, 4), DMODEL>>>(fa);

    // launches 1-3: CSR build (independent of the GEMMs)
    fill_cnt<<<256, 256>>>(cnt_p, NP, cnt_a, NA);
    hist2<<<2048, 256>>>(dst_ap, E_ap, cnt_p, dst_pa, E_pa, cnt_a);
    scan2<<<1, 1024>>>(cnt_p, NP, off_p, cur_p, cnt_a, NA, off_a, cur_a);

    // launches 4-5: fused QKV projections (launch 5 = papers, captured by ncu)
    int gb_p = (NP + DMODEL - 1) / DMODEL;
    int gb_a = (NA + DMODEL - 1) / DMODEL;
    gemm_qkv3<<<gb_a, 256, SMEM>>>(x_a, Wq_a, bq_a, q_a,
                                   Wk_ap, bk_ap, k_ap,
                                   Wv_ap, bv_ap, v_ap, NA);
    gemm_qkv3<<<gb_p, 256, SMEM>>>(x_p, Wq_p, bq_p, q_p,
                                   Wk_pa, bk_pa, k_pa,
                                   Wv_pa, bv_pa, v_pa, NP);

    // launches 6-7: logits + ev compaction
    int gw_ap = (E_ap * 32 + 255) / 256;
    int gw_pa = (E_pa * 32 + 255) / 256;
    edge_logits_fill<<<gw_ap, 256>>>(k_ap, q_p, src_ap, dst_ap, p_rel_ap,
                                     cur_p, eev_p, esrc_p, E_ap);
    edge_logits_fill<<<gw_pa, 256>>>(k_pa, q_a, src_pa, dst_pa, p_rel_pa,
                                     cur_a, eev_a, esrc_a, E_pa);

    // launches 8-9: per-dst aggregation (normalized, atomic-free)
    node_aggregate<<<(NP * 32 + 255) / 256, 256>>>(v_ap, off_p, esrc_p, eev_p, agg_p, NP);
    node_aggregate<<<(NA * 32 + 255) / 256, 256>>>(v_pa, off_a, esrc_a, eev_a, agg_a, NA);

    // launches 10-11: output projections + skip blend
    gemm_out<<<gb_p, 256, SMEM>>>(agg_p, Wa_p, ba_p, skip_p, x_p, out, NP);
    gemm_out<<<gb_a, 256, SMEM>>>(agg_a, Wa_a, ba_a, skip_a, x_a,
                                  out + (size_t)NP * DMODEL, NA);
}

// round 4
// speedup vs baseline: 1.1172x; 1.1172x over previous
#include <cuda_runtime.h>
#include <math.h>
#include <stdint.h>

#define NP 100000
#define NA 50000
#define EMAX 500000
#define DMODEL 128
#define NH 8
#define HDIM 16

#define SCAN_E 4096   // elements per scan block (1024 threads x 4)
#define NBP ((NP + SCAN_E - 1) / SCAN_E)   // 25
#define NBA ((NA + SCAN_E - 1) / SCAN_E)   // 13

// ---------------- scratch (device globals; no allocation allowed) ----------------
__device__ float g_Wk_ap[DMODEL * DMODEL];
__device__ float g_Wv_ap[DMODEL * DMODEL];
__device__ float g_Wk_pa[DMODEL * DMODEL];
__device__ float g_Wv_pa[DMODEL * DMODEL];
__device__ float g_bk_ap[DMODEL];
__device__ float g_bv_ap[DMODEL];
__device__ float g_bk_pa[DMODEL];
__device__ float g_bv_pa[DMODEL];

__device__ float g_q_p[(size_t)NP * DMODEL];
__device__ float g_k_pa[(size_t)NP * DMODEL];
__device__ float g_v_pa[(size_t)NP * DMODEL];
__device__ float g_q_a[(size_t)NA * DMODEL];
__device__ float g_k_ap[(size_t)NA * DMODEL];
__device__ float g_v_ap[(size_t)NA * DMODEL];

// CSR-by-dst machinery
__device__ int g_cnt_p[NP];
__device__ int g_cnt_a[NA];
__device__ int g_off_p[NP + 1];
__device__ int g_off_a[NA + 1];
__device__ int g_cur_p[NP];
__device__ int g_cur_a[NA];
__device__ int g_partials[NBP + NBA];
__device__ int g_esrc_p[EMAX];
__device__ int g_esrc_a[EMAX];
__device__ float g_eev_p[(size_t)EMAX * NH];
__device__ float g_eev_a[(size_t)EMAX * NH];

__device__ float g_agg_p[(size_t)NP * DMODEL];
__device__ float g_agg_a[(size_t)NA * DMODEL];

// ---------------- packed f32x2 helpers (FFMA2) ----------------
__device__ __forceinline__ void fma2(unsigned long long& c,
                                     unsigned long long a, unsigned long long b) {
    asm("fma.rn.f32x2 %0, %1, %2, %0;" : "+l"(c) : "l"(a), "l"(b));
}
__device__ __forceinline__ unsigned long long dup2(float x) {
    unsigned long long r;
    unsigned int xb = __float_as_uint(x);
    asm("mov.b64 %0, {%1, %1};" : "=l"(r) : "r"(xb));
    return r;
}
__device__ __forceinline__ float lo32(unsigned long long v) {
    return __uint_as_float((unsigned int)v);
}
__device__ __forceinline__ float hi32(unsigned long long v) {
    return __uint_as_float((unsigned int)(v >> 32));
}

// ---------------- setup kernels ----------------
struct FuseArgs {
    const float* W[4];
    const float* b[4];
    const float* rel[4];
    float* We[4];
    float* be[4];
};

__global__ void fuse_all(FuseArgs a) {
    int m = blockIdx.y;
    int k = blockIdx.x;
    int tid = threadIdx.x;
    int h = tid >> 4;
    int e = tid & 15;
    const float* r = a.rel[m] + h * HDIM * HDIM;
    const float* wrow = a.W[m] + k * DMODEL + h * HDIM;
    float s = 0.0f;
#pragma unroll
    for (int d = 0; d < HDIM; d++) s += wrow[d] * r[d * HDIM + e];
    a.We[m][k * DMODEL + tid] = s;
    if (k == 0) {
        const float* bb = a.b[m] + h * HDIM;
        float sb = 0.0f;
#pragma unroll
        for (int d = 0; d < HDIM; d++) sb += bb[d] * r[d * HDIM + e];
        a.be[m][tid] = sb;
    }
}

__global__ void fill_cnt(int* __restrict__ c0, int n0, int* __restrict__ c1, int n1) {
    int i = blockIdx.x * blockDim.x + threadIdx.x;
    int stride = gridDim.x * blockDim.x;
    for (; i < n0 + n1; i += stride) {
        if (i < n0) c0[i] = 0;
        else c1[i - n0] = 0;
    }
}

__global__ void hist2(const int* __restrict__ d0, int E0, int* __restrict__ c0,
                      const int* __restrict__ d1, int E1, int* __restrict__ c1) {
    int i = blockIdx.x * blockDim.x + threadIdx.x;
    int stride = gridDim.x * blockDim.x;
    for (; i < E0 + E1; i += stride) {
        if (i < E0) atomicAdd(&c0[d0[i]], 1);
        else atomicAdd(&c1[d1[i - E0]], 1);
    }
}

// ---------------- parallel 3-phase scan ----------------
// phase 1: per-block local exclusive scan (4096 elems/block), block totals -> partials
__global__ __launch_bounds__(1024) void scan_local(
        const int* __restrict__ cnt_p, const int* __restrict__ cnt_a,
        int* __restrict__ off_p, int* __restrict__ off_a,
        int* __restrict__ partials) {
    __shared__ int wsum[32];
    int b = blockIdx.x;
    const int* cnt;
    int* off;
    int n, base;
    if (b < NBP) { cnt = cnt_p; off = off_p; n = NP; base = b * SCAN_E; }
    else { cnt = cnt_a; off = off_a; n = NA; base = (b - NBP) * SCAN_E; }
    int tid = threadIdx.x;
    int lane = tid & 31;
    int wid = tid >> 5;
    int i = base + tid * 4;

    int4 v = make_int4(0, 0, 0, 0);
    if (i < n) v = *(const int4*)&cnt[i];   // n % 4 == 0 for both arrays
    int s0 = v.x;
    int s1 = s0 + v.y;
    int s2 = s1 + v.z;
    int s3 = s2 + v.w;
    int x = s3;
#pragma unroll
    for (int d = 1; d < 32; d <<= 1) {
        int t = __shfl_up_sync(0xffffffffu, x, d);
        if (lane >= d) x += t;
    }
    if (lane == 31) wsum[wid] = x;
    __syncthreads();
    if (wid == 0) {
        int s = wsum[lane];
#pragma unroll
        for (int d = 1; d < 32; d <<= 1) {
            int t = __shfl_up_sync(0xffffffffu, s, d);
            if (lane >= d) s += t;
        }
        wsum[lane] = s;
    }
    __syncthreads();
    int excl = (wid ? wsum[wid - 1] : 0) + (x - s3);
    if (i < n) {
        int4 o;
        o.x = excl;
        o.y = excl + s0;
        o.z = excl + s1;
        o.w = excl + s2;
        *(int4*)&off[i] = o;
    }
    if (tid == 0) partials[b] = wsum[31];
}

// phase 2: exclusive scan of block partials (tiny, single thread), write totals
__global__ void scan_partials(int* __restrict__ partials,
                              int* __restrict__ off_p, int* __restrict__ off_a) {
    if (threadIdx.x == 0) {
        int run = 0;
        for (int b = 0; b < NBP; b++) {
            int t = partials[b];
            partials[b] = run;
            run += t;
        }
        off_p[NP] = run;
        run = 0;
        for (int b = NBP; b < NBP + NBA; b++) {
            int t = partials[b];
            partials[b] = run;
            run += t;
        }
        off_a[NA] = run;
    }
}

// phase 3: add block bases, emit final off and cur
__global__ __launch_bounds__(1024) void add_base(
        int* __restrict__ off_p, int* __restrict__ off_a,
        int* __restrict__ cur_p, int* __restrict__ cur_a,
        const int* __restrict__ partials) {
    int b = blockIdx.x;
    int* off;
    int* cur;
    int n, base;
    if (b < NBP) { off = off_p; cur = cur_p; n = NP; base = b * SCAN_E; }
    else { off = off_a; cur = cur_a; n = NA; base = (b - NBP) * SCAN_E; }
    int add = partials[b];
    int i = base + threadIdx.x * 4;
    if (i < n) {
        int4 o = *(const int4*)&off[i];
        o.x += add; o.y += add; o.z += add; o.w += add;
        *(int4*)&off[i] = o;
        *(int4*)&cur[i] = o;
    }
}

// ---------------- shared-memory GEMM core: 128x128 tile, 8x8 per thread, FFMA2 ----------
__device__ __forceinline__ void mm_core(const float* __restrict__ Xs,
                                        const float* __restrict__ Ws,
                                        int rg, int c4,
                                        unsigned long long acc[8][4]) {
#pragma unroll
    for (int i = 0; i < 8; i++)
#pragma unroll
        for (int j = 0; j < 4; j++) acc[i][j] = 0ull;

#pragma unroll 4
    for (int k = 0; k < DMODEL; k++) {
        ulonglong2 wa = *(const ulonglong2*)&Ws[k * DMODEL + c4];
        ulonglong2 wb = *(const ulonglong2*)&Ws[k * DMODEL + c4 + 64];
#pragma unroll
        for (int i = 0; i < 8; i++) {
            unsigned long long x2 = dup2(Xs[(rg + i) * DMODEL + k]);
            fma2(acc[i][0], x2, wa.x);
            fma2(acc[i][1], x2, wa.y);
            fma2(acc[i][2], x2, wb.x);
            fma2(acc[i][3], x2, wb.y);
        }
    }
}

// ---------------- fused Q/K/V projection ----------------
__global__ __launch_bounds__(256) void gemm_qkv3(
        const float* __restrict__ X,
        const float* __restrict__ W0, const float* __restrict__ b0, float* __restrict__ Y0,
        const float* __restrict__ W1, const float* __restrict__ b1, float* __restrict__ Y1,
        const float* __restrict__ W2, const float* __restrict__ b2, float* __restrict__ Y2,
        int N) {
    extern __shared__ float sm[];
    float* Xs = sm;
    float* Ws = sm + DMODEL * DMODEL;
    int tid = threadIdx.x;
    int row0 = blockIdx.x * DMODEL;

    {
        const float4* Xg = (const float4*)X;
        float4* Xsv = (float4*)Xs;
#pragma unroll
        for (int i = tid; i < DMODEL * 32; i += 256) {
            int gr = row0 + (i >> 5);
            float4 v = make_float4(0.f, 0.f, 0.f, 0.f);
            if (gr < N) v = Xg[(size_t)gr * 32 + (i & 31)];
            Xsv[i] = v;
        }
    }

    int rg = (tid >> 4) * 8;
    int c4 = (tid & 15) * 4;
    const float* Wm[3] = {W0, W1, W2};
    const float* bm[3] = {b0, b1, b2};
    float* Ym[3] = {Y0, Y1, Y2};

#pragma unroll 1
    for (int m = 0; m < 3; m++) {
        {
            const float4* Wg = (const float4*)Wm[m];
            float4* Wsv = (float4*)Ws;
#pragma unroll
            for (int i = tid; i < DMODEL * 32; i += 256) Wsv[i] = Wg[i];
        }
        __syncthreads();

        unsigned long long acc[8][4];
        mm_core(Xs, Ws, rg, c4, acc);

        const float* bias = bm[m];
        float4 bv0 = *(const float4*)&bias[c4];
        float4 bv1 = *(const float4*)&bias[c4 + 64];
        float* Y = Ym[m];
#pragma unroll
        for (int i = 0; i < 8; i++) {
            int gr = row0 + rg + i;
            if (gr < N) {
                float4 o0, o1;
                o0.x = lo32(acc[i][0]) + bv0.x;
                o0.y = hi32(acc[i][0]) + bv0.y;
                o0.z = lo32(acc[i][1]) + bv0.z;
                o0.w = hi32(acc[i][1]) + bv0.w;
                o1.x = lo32(acc[i][2]) + bv1.x;
                o1.y = hi32(acc[i][2]) + bv1.y;
                o1.z = lo32(acc[i][3]) + bv1.z;
                o1.w = hi32(acc[i][3]) + bv1.w;
                *(float4*)&Y[(size_t)gr * DMODEL + c4] = o0;
                *(float4*)&Y[(size_t)gr * DMODEL + c4 + 64] = o1;
            }
        }
        __syncthreads();
    }
}

// ---------------- output GEMM: Y = al*(agg @ W + b) + (1-al)*Xres ----------------
__global__ __launch_bounds__(256) void gemm_out(
        const float* __restrict__ Xagg,
        const float* __restrict__ W, const float* __restrict__ bias,
        const float* __restrict__ skip, const float* __restrict__ Xres,
        float* __restrict__ Y, int N) {
    extern __shared__ float sm[];
    float* Xs = sm;
    float* Ws = sm + DMODEL * DMODEL;
    int tid = threadIdx.x;
    int row0 = blockIdx.x * DMODEL;

    {
        const float4* Xg = (const float4*)Xagg;
        float4* Xsv = (float4*)Xs;
#pragma unroll
        for (int i = tid; i < DMODEL * 32; i += 256) {
            int gr = row0 + (i >> 5);
            float4 v = make_float4(0.f, 0.f, 0.f, 0.f);
            if (gr < N) v = Xg[(size_t)gr * 32 + (i & 31)];
            Xsv[i] = v;
        }
        const float4* Wg = (const float4*)W;
        float4* Wsv = (float4*)Ws;
#pragma unroll
        for (int i = tid; i < DMODEL * 32; i += 256) Wsv[i] = Wg[i];
    }
    __syncthreads();

    int rg = (tid >> 4) * 8;
    int c4 = (tid & 15) * 4;
    unsigned long long acc[8][4];
    mm_core(Xs, Ws, rg, c4, acc);

    float al = 1.0f / (1.0f + __expf(-skip[0]));
    float be = 1.0f - al;
    float4 bv0 = *(const float4*)&bias[c4];
    float4 bv1 = *(const float4*)&bias[c4 + 64];
#pragma unroll
    for (int i = 0; i < 8; i++) {
        int gr = row0 + rg + i;
        if (gr < N) {
            float4 x0 = *(const float4*)&Xres[(size_t)gr * DMODEL + c4];
            float4 x1 = *(const float4*)&Xres[(size_t)gr * DMODEL + c4 + 64];
            float4 o0, o1;
            o0.x = al * (lo32(acc[i][0]) + bv0.x) + be * x0.x;
            o0.y = al * (hi32(acc[i][0]) + bv0.y) + be * x0.y;
            o0.z = al * (lo32(acc[i][1]) + bv0.z) + be * x0.z;
            o0.w = al * (hi32(acc[i][1]) + bv0.w) + be * x0.w;
            o1.x = al * (lo32(acc[i][2]) + bv1.x) + be * x1.x;
            o1.y = al * (hi32(acc[i][2]) + bv1.y) + be * x1.y;
            o1.z = al * (lo32(acc[i][3]) + bv1.z) + be * x1.z;
            o1.w = al * (hi32(acc[i][3]) + bv1.w) + be * x1.w;
            *(float4*)&Y[(size_t)gr * DMODEL + c4] = o0;
            *(float4*)&Y[(size_t)gr * DMODEL + c4 + 64] = o1;
        }
    }
}

// ---------------- edge pass C: logits -> ev, compacted by dst via cursor ----------------
__global__ void edge_logits_fill(const float* __restrict__ K, const float* __restrict__ Q,
                                 const int* __restrict__ src, const int* __restrict__ dst,
                                 const float* __restrict__ p_rel,
                                 int* __restrict__ cur,
                                 float* __restrict__ eev, int* __restrict__ esrc, int E) {
    int g = blockIdx.x * blockDim.x + threadIdx.x;
    int e = g >> 5;
    int lane = g & 31;
    if (e >= E) return;
    int s = src[e];
    int d = dst[e];
    float4 kv = ((const float4*)(K + (size_t)s * DMODEL))[lane];
    float4 qv = ((const float4*)(Q + (size_t)d * DMODEL))[lane];
    float p = kv.x * qv.x + kv.y * qv.y + kv.z * qv.z + kv.w * qv.w;
    p += __shfl_xor_sync(0xffffffffu, p, 1);
    p += __shfl_xor_sync(0xffffffffu, p, 2);
    int h = lane >> 2;
    float ev = __expf(p * __ldg(&p_rel[h]) * 0.25f);   // / sqrt(D=16)
    int pos = 0;
    if (lane == 0) pos = atomicAdd(&cur[d], 1);
    pos = __shfl_sync(0xffffffffu, pos, 0);
    float evl = __shfl_sync(0xffffffffu, ev, (lane & 7) * 4);
    if (lane < 8) eev[(size_t)pos * NH + lane] = evl;
    else if (lane == 8) esrc[pos] = s;
}

// ---------------- edge pass D: per-dst gather-aggregate, normalized plain store ---------
__global__ void node_aggregate(const float* __restrict__ V,
                               const int* __restrict__ off, const int* __restrict__ esrc,
                               const float* __restrict__ eev,
                               float* __restrict__ agg, int N) {
    int g = blockIdx.x * blockDim.x + threadIdx.x;
    int w = g >> 5;
    int lane = g & 31;
    if (w >= N) return;
    int j0 = off[w];
    int j1 = off[w + 1];
    int h = lane >> 2;
    float4 acc = make_float4(0.f, 0.f, 0.f, 0.f);
    float den = 0.0f;
    for (int j = j0; j < j1; j++) {
        float ev = __ldg(&eev[(size_t)j * NH + h]);
        int s = __ldg(&esrc[j]);
        float4 v = ((const float4*)(V + (size_t)s * DMODEL))[lane];
        acc.x += ev * v.x;
        acc.y += ev * v.y;
        acc.z += ev * v.z;
        acc.w += ev * v.w;
        den += ev;
    }
    float inv = 1.0f / (den + 1e-16f);
    float4 o;
    o.x = acc.x * inv;
    o.y = acc.y * inv;
    o.z = acc.z * inv;
    o.w = acc.w * inv;
    ((float4*)(agg + (size_t)w * DMODEL))[lane] = o;
}

// ---------------- launch ----------------
extern "C" void kernel_launch(void* const* d_in, const int* in_sizes, int n_in,
                              void* d_out, int out_size) {
    const float* x_p = (const float*)d_in[0];
    const float* x_a = (const float*)d_in[1];
    const int* src_ap = (const int*)d_in[2];
    const int* dst_ap = (const int*)d_in[3];
    const int* src_pa = (const int*)d_in[4];
    const int* dst_pa = (const int*)d_in[5];
    const float* Wq_p = (const float*)d_in[6];
    const float* bq_p = (const float*)d_in[7];
    const float* Wk_p = (const float*)d_in[8];
    const float* bk_p = (const float*)d_in[9];
    const float* Wv_p = (const float*)d_in[10];
    const float* bv_p = (const float*)d_in[11];
    const float* Wa_p = (const float*)d_in[12];
    const float* ba_p = (const float*)d_in[13];
    const float* skip_p = (const float*)d_in[14];
    const float* Wq_a = (const float*)d_in[15];
    const float* bq_a = (const float*)d_in[16];
    const float* Wk_a = (const float*)d_in[17];
    const float* bk_a = (const float*)d_in[18];
    const float* Wv_a = (const float*)d_in[19];
    const float* bv_a = (const float*)d_in[20];
    const float* Wa_a = (const float*)d_in[21];
    const float* ba_a = (const float*)d_in[22];
    const float* skip_a = (const float*)d_in[23];
    const float* a_rel_ap = (const float*)d_in[24];
    const float* m_rel_ap = (const float*)d_in[25];
    const float* p_rel_ap = (const float*)d_in[26];
    const float* a_rel_pa = (const float*)d_in[27];
    const float* m_rel_pa = (const float*)d_in[28];
    const float* p_rel_pa = (const float*)d_in[29];
    float* out = (float*)d_out;

    int E_ap = in_sizes[2];
    int E_pa = in_sizes[4];

    float *Wk_ap, *Wv_ap, *Wk_pa, *Wv_pa, *bk_ap, *bv_ap, *bk_pa, *bv_pa;
    float *q_p, *k_pa, *v_pa, *q_a, *k_ap, *v_ap, *agg_p, *agg_a;
    float *eev_p, *eev_a;
    int *cnt_p, *cnt_a, *off_p, *off_a, *cur_p, *cur_a, *esrc_p, *esrc_a, *partials;
    cudaGetSymbolAddress((void**)&Wk_ap, g_Wk_ap);
    cudaGetSymbolAddress((void**)&Wv_ap, g_Wv_ap);
    cudaGetSymbolAddress((void**)&Wk_pa, g_Wk_pa);
    cudaGetSymbolAddress((void**)&Wv_pa, g_Wv_pa);
    cudaGetSymbolAddress((void**)&bk_ap, g_bk_ap);
    cudaGetSymbolAddress((void**)&bv_ap, g_bv_ap);
    cudaGetSymbolAddress((void**)&bk_pa, g_bk_pa);
    cudaGetSymbolAddress((void**)&bv_pa, g_bv_pa);
    cudaGetSymbolAddress((void**)&q_p, g_q_p);
    cudaGetSymbolAddress((void**)&k_pa, g_k_pa);
    cudaGetSymbolAddress((void**)&v_pa, g_v_pa);
    cudaGetSymbolAddress((void**)&q_a, g_q_a);
    cudaGetSymbolAddress((void**)&k_ap, g_k_ap);
    cudaGetSymbolAddress((void**)&v_ap, g_v_ap);
    cudaGetSymbolAddress((void**)&agg_p, g_agg_p);
    cudaGetSymbolAddress((void**)&agg_a, g_agg_a);
    cudaGetSymbolAddress((void**)&eev_p, g_eev_p);
    cudaGetSymbolAddress((void**)&eev_a, g_eev_a);
    cudaGetSymbolAddress((void**)&cnt_p, g_cnt_p);
    cudaGetSymbolAddress((void**)&cnt_a, g_cnt_a);
    cudaGetSymbolAddress((void**)&off_p, g_off_p);
    cudaGetSymbolAddress((void**)&off_a, g_off_a);
    cudaGetSymbolAddress((void**)&cur_p, g_cur_p);
    cudaGetSymbolAddress((void**)&cur_a, g_cur_a);
    cudaGetSymbolAddress((void**)&esrc_p, g_esrc_p);
    cudaGetSymbolAddress((void**)&esrc_a, g_esrc_a);
    cudaGetSymbolAddress((void**)&partials, g_partials);

    const int SMEM = 2 * DMODEL * DMODEL * (int)sizeof(float);  // 128 KB
    cudaFuncSetAttribute(gemm_qkv3, cudaFuncAttributeMaxDynamicSharedMemorySize, SMEM);
    cudaFuncSetAttribute(gemm_out, cudaFuncAttributeMaxDynamicSharedMemorySize, SMEM);

    // launch 0: fold relation matrices into projection weights
    FuseArgs fa;
    fa.W[0] = Wk_a; fa.b[0] = bk_a; fa.rel[0] = a_rel_ap; fa.We[0] = Wk_ap; fa.be[0] = bk_ap;
    fa.W[1] = Wv_a; fa.b[1] = bv_a; fa.rel[1] = m_rel_ap; fa.We[1] = Wv_ap; fa.be[1] = bv_ap;
    fa.W[2] = Wk_p; fa.b[2] = bk_p; fa.rel[2] = a_rel_pa; fa.We[2] = Wk_pa; fa.be[2] = bk_pa;
    fa.W[3] = Wv_p; fa.b[3] = bv_p; fa.rel[3] = m_rel_pa; fa.We[3] = Wv_pa; fa.be[3] = bv_pa;
    fuse_all<<<dim3(DMODEL, 4), DMODEL>>>(fa);

    // launches 1-3: CSR histogram + local scan
    fill_cnt<<<256, 256>>>(cnt_p, NP, cnt_a, NA);
    hist2<<<2048, 256>>>(dst_ap, E_ap, cnt_p, dst_pa, E_pa, cnt_a);
    scan_local<<<NBP + NBA, 1024>>>(cnt_p, cnt_a, off_p, off_a, partials);

    // launches 4-5: fused QKV projections (launch 5 = paper GEMM, ncu window)
    int gb_p = (NP + DMODEL - 1) / DMODEL;
    int gb_a = (NA + DMODEL - 1) / DMODEL;
    gemm_qkv3<<<gb_a, 256, SMEM>>>(x_a, Wq_a, bq_a, q_a,
                                   Wk_ap, bk_ap, k_ap,
                                   Wv_ap, bv_ap, v_ap, NA);
    gemm_qkv3<<<gb_p, 256, SMEM>>>(x_p, Wq_p, bq_p, q_p,
                                   Wk_pa, bk_pa, k_pa,
                                   Wv_pa, bv_pa, v_pa, NP);

    // launches 6-7: finish scan (tiny)
    scan_partials<<<1, 32>>>(partials, off_p, off_a);
    add_base<<<NBP + NBA, 1024>>>(off_p, off_a, cur_p, cur_a, partials);

    // launches 8-9: logits + ev compaction
    int gw_ap = (E_ap * 32 + 255) / 256;
    int gw_pa = (E_pa * 32 + 255) / 256;
    edge_logits_fill<<<gw_ap, 256>>>(k_ap, q_p, src_ap, dst_ap, p_rel_ap,
                                     cur_p, eev_p, esrc_p, E_ap);
    edge_logits_fill<<<gw_pa, 256>>>(k_pa, q_a, src_pa, dst_pa, p_rel_pa,
                                     cur_a, eev_a, esrc_a, E_pa);

    // launches 10-11: per-dst aggregation (atomic-free, normalized)
    node_aggregate<<<(NP * 32 + 255) / 256, 256>>>(v_ap, off_p, esrc_p, eev_p, agg_p, NP);
    node_aggregate<<<(NA * 32 + 255) / 256, 256>>>(v_pa, off_a, esrc_a, eev_a, agg_a, NA);

    // launches 12-13: output projections + skip blend
    gemm_out<<<gb_p, 256, SMEM>>>(agg_p, Wa_p, ba_p, skip_p, x_p, out, NP);
    gemm_out<<<gb_a, 256, SMEM>>>(agg_a, Wa_a, ba_a, skip_a, x_a,
                                  out + (size_t)NP * DMODEL, NA);
}

// round 5
// speedup vs baseline: 1.1963x; 1.0708x over previous
#include <cuda_runtime.h>
#include <math.h>
#include <stdint.h>

#define NP 100000
#define NA 50000
#define EMAX 500000
#define DMODEL 128
#define NH 8
#define HDIM 16
#define KVLD 256   // interleaved K|V row stride

#define SCAN_E 4096
#define NBP ((NP + SCAN_E - 1) / SCAN_E)   // 25
#define NBA ((NA + SCAN_E - 1) / SCAN_E)   // 13

// ---------------- scratch (device globals; no allocation allowed) ----------------
__device__ float g_Wk_ap[DMODEL * DMODEL];
__device__ float g_Wv_ap[DMODEL * DMODEL];
__device__ float g_Wk_pa[DMODEL * DMODEL];
__device__ float g_Wv_pa[DMODEL * DMODEL];
__device__ float g_bk_ap[DMODEL];
__device__ float g_bv_ap[DMODEL];
__device__ float g_bk_pa[DMODEL];
__device__ float g_bv_pa[DMODEL];

__device__ float g_q_p[(size_t)NP * DMODEL];     // pre-scaled by p_rel_ap/4
__device__ float g_q_a[(size_t)NA * DMODEL];     // pre-scaled by p_rel_pa/4
__device__ float g_kv_ap[(size_t)NA * KVLD];     // author K|V for ap edges
__device__ float g_kv_pa[(size_t)NP * KVLD];     // paper  K|V for pa edges

// CSR-by-dst machinery
__device__ int g_cnt_p[NP];
__device__ int g_cnt_a[NA];
__device__ int g_off_p[NP + 1];
__device__ int g_off_a[NA + 1];
__device__ int g_cur_p[NP];
__device__ int g_cur_a[NA];
__device__ int g_partials[NBP + NBA];
__device__ int g_esrc_p[EMAX];
__device__ int g_esrc_a[EMAX];

__device__ float g_agg_p[(size_t)NP * DMODEL];
__device__ float g_agg_a[(size_t)NA * DMODEL];

// ---------------- packed f32x2 helpers (FFMA2) ----------------
__device__ __forceinline__ void fma2(unsigned long long& c,
                                     unsigned long long a, unsigned long long b) {
    asm("fma.rn.f32x2 %0, %1, %2, %0;" : "+l"(c) : "l"(a), "l"(b));
}
__device__ __forceinline__ unsigned long long dup2(float x) {
    unsigned long long r;
    unsigned int xb = __float_as_uint(x);
    asm("mov.b64 %0, {%1, %1};" : "=l"(r) : "r"(xb));
    return r;
}
__device__ __forceinline__ float lo32(unsigned long long v) {
    return __uint_as_float((unsigned int)v);
}
__device__ __forceinline__ float hi32(unsigned long long v) {
    return __uint_as_float((unsigned int)(v >> 32));
}

// ---------------- setup kernels ----------------
struct FuseArgs {
    const float* W[4];
    const float* b[4];
    const float* rel[4];
    float* We[4];
    float* be[4];
};

__global__ void fuse_all(FuseArgs a) {
    int m = blockIdx.y;
    int k = blockIdx.x;
    int tid = threadIdx.x;
    int h = tid >> 4;
    int e = tid & 15;
    const float* r = a.rel[m] + h * HDIM * HDIM;
    const float* wrow = a.W[m] + k * DMODEL + h * HDIM;
    float s = 0.0f;
#pragma unroll
    for (int d = 0; d < HDIM; d++) s += wrow[d] * r[d * HDIM + e];
    a.We[m][k * DMODEL + tid] = s;
    if (k == 0) {
        const float* bb = a.b[m] + h * HDIM;
        float sb = 0.0f;
#pragma unroll
        for (int d = 0; d < HDIM; d++) sb += bb[d] * r[d * HDIM + e];
        a.be[m][tid] = sb;
    }
}

__global__ void fill_cnt(int* __restrict__ c0, int n0, int* __restrict__ c1, int n1) {
    int i = blockIdx.x * blockDim.x + threadIdx.x;
    int stride = gridDim.x * blockDim.x;
    for (; i < n0 + n1; i += stride) {
        if (i < n0) c0[i] = 0;
        else c1[i - n0] = 0;
    }
}

__global__ void hist2(const int* __restrict__ d0, int E0, int* __restrict__ c0,
                      const int* __restrict__ d1, int E1, int* __restrict__ c1) {
    int i = blockIdx.x * blockDim.x + threadIdx.x;
    int stride = gridDim.x * blockDim.x;
    for (; i < E0 + E1; i += stride) {
        if (i < E0) atomicAdd(&c0[d0[i]], 1);
        else atomicAdd(&c1[d1[i - E0]], 1);
    }
}

// ---------------- parallel 3-phase scan ----------------
__global__ __launch_bounds__(1024) void scan_local(
        const int* __restrict__ cnt_p, const int* __restrict__ cnt_a,
        int* __restrict__ off_p, int* __restrict__ off_a,
        int* __restrict__ partials) {
    __shared__ int wsum[32];
    int b = blockIdx.x;
    const int* cnt;
    int* off;
    int n, base;
    if (b < NBP) { cnt = cnt_p; off = off_p; n = NP; base = b * SCAN_E; }
    else { cnt = cnt_a; off = off_a; n = NA; base = (b - NBP) * SCAN_E; }
    int tid = threadIdx.x;
    int lane = tid & 31;
    int wid = tid >> 5;
    int i = base + tid * 4;

    int4 v = make_int4(0, 0, 0, 0);
    if (i < n) v = *(const int4*)&cnt[i];
    int s0 = v.x;
    int s1 = s0 + v.y;
    int s2 = s1 + v.z;
    int s3 = s2 + v.w;
    int x = s3;
#pragma unroll
    for (int d = 1; d < 32; d <<= 1) {
        int t = __shfl_up_sync(0xffffffffu, x, d);
        if (lane >= d) x += t;
    }
    if (lane == 31) wsum[wid] = x;
    __syncthreads();
    if (wid == 0) {
        int s = wsum[lane];
#pragma unroll
        for (int d = 1; d < 32; d <<= 1) {
            int t = __shfl_up_sync(0xffffffffu, s, d);
            if (lane >= d) s += t;
        }
        wsum[lane] = s;
    }
    __syncthreads();
    int excl = (wid ? wsum[wid - 1] : 0) + (x - s3);
    if (i < n) {
        int4 o;
        o.x = excl;
        o.y = excl + s0;
        o.z = excl + s1;
        o.w = excl + s2;
        *(int4*)&off[i] = o;
    }
    if (tid == 0) partials[b] = wsum[31];
}

__global__ void scan_partials(int* __restrict__ partials,
                              int* __restrict__ off_p, int* __restrict__ off_a) {
    if (threadIdx.x == 0) {
        int run = 0;
        for (int b = 0; b < NBP; b++) {
            int t = partials[b];
            partials[b] = run;
            run += t;
        }
        off_p[NP] = run;
        run = 0;
        for (int b = NBP; b < NBP + NBA; b++) {
            int t = partials[b];
            partials[b] = run;
            run += t;
        }
        off_a[NA] = run;
    }
}

__global__ __launch_bounds__(1024) void add_base(
        int* __restrict__ off_p, int* __restrict__ off_a,
        int* __restrict__ cur_p, int* __restrict__ cur_a,
        const int* __restrict__ partials) {
    int b = blockIdx.x;
    int* off;
    int* cur;
    int n, base;
    if (b < NBP) { off = off_p; cur = cur_p; n = NP; base = b * SCAN_E; }
    else { off = off_a; cur = cur_a; n = NA; base = (b - NBP) * SCAN_E; }
    int add = partials[b];
    int i = base + threadIdx.x * 4;
    if (i < n) {
        int4 o = *(const int4*)&off[i];
        o.x += add; o.y += add; o.z += add; o.w += add;
        *(int4*)&off[i] = o;
        *(int4*)&cur[i] = o;
    }
}

// ---------------- bucket src ids by dst (both edge types) ----------------
__global__ void build_esrc(const int* __restrict__ src0, const int* __restrict__ dst0,
                           int E0, int* __restrict__ cur0, int* __restrict__ out0,
                           const int* __restrict__ src1, const int* __restrict__ dst1,
                           int E1, int* __restrict__ cur1, int* __restrict__ out1) {
    int i = blockIdx.x * blockDim.x + threadIdx.x;
    int stride = gridDim.x * blockDim.x;
    for (; i < E0 + E1; i += stride) {
        if (i < E0) {
            int pos = atomicAdd(&cur0[dst0[i]], 1);
            out0[pos] = src0[i];
        } else {
            int j = i - E0;
            int pos = atomicAdd(&cur1[dst1[j]], 1);
            out1[pos] = src1[j];
        }
    }
}

// ---------------- shared-memory GEMM core: 128x128 tile, 8x8 per thread, FFMA2 ----------
__device__ __forceinline__ void mm_core(const float* __restrict__ Xs,
                                        const float* __restrict__ Ws,
                                        int rg, int c4,
                                        unsigned long long acc[8][4]) {
#pragma unroll
    for (int i = 0; i < 8; i++)
#pragma unroll
        for (int j = 0; j < 4; j++) acc[i][j] = 0ull;

#pragma unroll 4
    for (int k = 0; k < DMODEL; k++) {
        ulonglong2 wa = *(const ulonglong2*)&Ws[k * DMODEL + c4];
        ulonglong2 wb = *(const ulonglong2*)&Ws[k * DMODEL + c4 + 64];
#pragma unroll
        for (int i = 0; i < 8; i++) {
            unsigned long long x2 = dup2(Xs[(rg + i) * DMODEL + k]);
            fma2(acc[i][0], x2, wa.x);
            fma2(acc[i][1], x2, wa.y);
            fma2(acc[i][2], x2, wb.x);
            fma2(acc[i][3], x2, wb.y);
        }
    }
}

// ---------------- fused Q/K/V projection with per-output row stride -------------
// Y0 (=q) additionally scaled per column by p_rel[col/16] * 0.25 (logit scale folded in).
__global__ __launch_bounds__(256) void gemm_qkv3(
        const float* __restrict__ X,
        const float* __restrict__ W0, const float* __restrict__ b0,
        float* __restrict__ Y0, int ld0, const float* __restrict__ prel,
        const float* __restrict__ W1, const float* __restrict__ b1,
        float* __restrict__ Y1, int ld1,
        const float* __restrict__ W2, const float* __restrict__ b2,
        float* __restrict__ Y2, int ld2,
        int N) {
    extern __shared__ float sm[];
    float* Xs = sm;
    float* Ws = sm + DMODEL * DMODEL;
    int tid = threadIdx.x;
    int row0 = blockIdx.x * DMODEL;

    {
        const float4* Xg = (const float4*)X;
        float4* Xsv = (float4*)Xs;
#pragma unroll
        for (int i = tid; i < DMODEL * 32; i += 256) {
            int gr = row0 + (i >> 5);
            float4 v = make_float4(0.f, 0.f, 0.f, 0.f);
            if (gr < N) v = Xg[(size_t)gr * 32 + (i & 31)];
            Xsv[i] = v;
        }
    }

    int rg = (tid >> 4) * 8;
    int c4 = (tid & 15) * 4;
    const float* Wm[3] = {W0, W1, W2};
    const float* bm[3] = {b0, b1, b2};
    float* Ym[3] = {Y0, Y1, Y2};
    int ldm[3] = {ld0, ld1, ld2};

#pragma unroll 1
    for (int m = 0; m < 3; m++) {
        {
            const float4* Wg = (const float4*)Wm[m];
            float4* Wsv = (float4*)Ws;
#pragma unroll
            for (int i = tid; i < DMODEL * 32; i += 256) Wsv[i] = Wg[i];
        }
        __syncthreads();

        unsigned long long acc[8][4];
        mm_core(Xs, Ws, rg, c4, acc);

        const float* bias = bm[m];
        float4 bv0 = *(const float4*)&bias[c4];
        float4 bv1 = *(const float4*)&bias[c4 + 64];
        float sca = 1.0f, scb = 1.0f;
        if (m == 0) {
            sca = __ldg(&prel[c4 >> 4]) * 0.25f;
            scb = __ldg(&prel[(c4 + 64) >> 4]) * 0.25f;
        }
        float* Y = Ym[m];
        int ld = ldm[m];
#pragma unroll
        for (int i = 0; i < 8; i++) {
            int gr = row0 + rg + i;
            if (gr < N) {
                float4 o0, o1;
                o0.x = (lo32(acc[i][0]) + bv0.x) * sca;
                o0.y = (hi32(acc[i][0]) + bv0.y) * sca;
                o0.z = (lo32(acc[i][1]) + bv0.z) * sca;
                o0.w = (hi32(acc[i][1]) + bv0.w) * sca;
                o1.x = (lo32(acc[i][2]) + bv1.x) * scb;
                o1.y = (hi32(acc[i][2]) + bv1.y) * scb;
                o1.z = (lo32(acc[i][3]) + bv1.z) * scb;
                o1.w = (hi32(acc[i][3]) + bv1.w) * scb;
                *(float4*)&Y[(size_t)gr * ld + c4] = o0;
                *(float4*)&Y[(size_t)gr * ld + c4 + 64] = o1;
            }
        }
        __syncthreads();
    }
}

// ---------------- output GEMM: Y = al*(agg @ W + b) + (1-al)*Xres ----------------
__global__ __launch_bounds__(256) void gemm_out(
        const float* __restrict__ Xagg,
        const float* __restrict__ W, const float* __restrict__ bias,
        const float* __restrict__ skip, const float* __restrict__ Xres,
        float* __restrict__ Y, int N) {
    extern __shared__ float sm[];
    float* Xs = sm;
    float* Ws = sm + DMODEL * DMODEL;
    int tid = threadIdx.x;
    int row0 = blockIdx.x * DMODEL;

    {
        const float4* Xg = (const float4*)Xagg;
        float4* Xsv = (float4*)Xs;
#pragma unroll
        for (int i = tid; i < DMODEL * 32; i += 256) {
            int gr = row0 + (i >> 5);
            float4 v = make_float4(0.f, 0.f, 0.f, 0.f);
            if (gr < N) v = Xg[(size_t)gr * 32 + (i & 31)];
            Xsv[i] = v;
        }
        const float4* Wg = (const float4*)W;
        float4* Wsv = (float4*)Ws;
#pragma unroll
        for (int i = tid; i < DMODEL * 32; i += 256) Wsv[i] = Wg[i];
    }
    __syncthreads();

    int rg = (tid >> 4) * 8;
    int c4 = (tid & 15) * 4;
    unsigned long long acc[8][4];
    mm_core(Xs, Ws, rg, c4, acc);

    float al = 1.0f / (1.0f + __expf(-skip[0]));
    float be = 1.0f - al;
    float4 bv0 = *(const float4*)&bias[c4];
    float4 bv1 = *(const float4*)&bias[c4 + 64];
#pragma unroll
    for (int i = 0; i < 8; i++) {
        int gr = row0 + rg + i;
        if (gr < N) {
            float4 x0 = *(const float4*)&Xres[(size_t)gr * DMODEL + c4];
            float4 x1 = *(const float4*)&Xres[(size_t)gr * DMODEL + c4 + 64];
            float4 o0, o1;
            o0.x = al * (lo32(acc[i][0]) + bv0.x) + be * x0.x;
            o0.y = al * (hi32(acc[i][0]) + bv0.y) + be * x0.y;
            o0.z = al * (lo32(acc[i][1]) + bv0.z) + be * x0.z;
            o0.w = al * (hi32(acc[i][1]) + bv0.w) + be * x0.w;
            o1.x = al * (lo32(acc[i][2]) + bv1.x) + be * x1.x;
            o1.y = al * (hi32(acc[i][2]) + bv1.y) + be * x1.y;
            o1.z = al * (lo32(acc[i][3]) + bv1.z) + be * x1.z;
            o1.w = al * (hi32(acc[i][3]) + bv1.w) + be * x1.w;
            *(float4*)&Y[(size_t)gr * DMODEL + c4] = o0;
            *(float4*)&Y[(size_t)gr * DMODEL + c4 + 64] = o1;
        }
    }
}

// ---------------- fused per-dst attention ----------------
// One warp per destination node. Q[dst] held in registers (logit scale pre-folded).
// Per edge: gather interleaved K|V row, logit -> exp -> accumulate. Single plain store.
__global__ void node_attn(const float* __restrict__ Q, const float* __restrict__ KV,
                          const int* __restrict__ off, const int* __restrict__ esrc,
                          float* __restrict__ agg, int N) {
    int g = blockIdx.x * blockDim.x + threadIdx.x;
    int w = g >> 5;
    int lane = g & 31;
    if (w >= N) return;
    float4 q = ((const float4*)(Q + (size_t)w * DMODEL))[lane];
    int j0 = off[w];
    int j1 = off[w + 1];
    float4 acc = make_float4(0.f, 0.f, 0.f, 0.f);
    float den = 0.0f;
    for (int j = j0; j < j1; j++) {
        int s = __ldg(&esrc[j]);
        const float4* kvrow = (const float4*)(KV + (size_t)s * KVLD);
        float4 k4 = __ldg(&kvrow[lane]);
        float p = k4.x * q.x + k4.y * q.y + k4.z * q.z + k4.w * q.w;
        p += __shfl_xor_sync(0xffffffffu, p, 1);
        p += __shfl_xor_sync(0xffffffffu, p, 2);
        float ev = __expf(p);                  // scale already folded into Q
        float4 v4 = __ldg(&kvrow[lane + 32]);  // V half
        acc.x += ev * v4.x;
        acc.y += ev * v4.y;
        acc.z += ev * v4.z;
        acc.w += ev * v4.w;
        den += ev;
    }
    float inv = 1.0f / (den + 1e-16f);
    float4 o;
    o.x = acc.x * inv;
    o.y = acc.y * inv;
    o.z = acc.z * inv;
    o.w = acc.w * inv;
    ((float4*)(agg + (size_t)w * DMODEL))[lane] = o;
}

// ---------------- launch ----------------
extern "C" void kernel_launch(void* const* d_in, const int* in_sizes, int n_in,
                              void* d_out, int out_size) {
    const float* x_p = (const float*)d_in[0];
    const float* x_a = (const float*)d_in[1];
    const int* src_ap = (const int*)d_in[2];
    const int* dst_ap = (const int*)d_in[3];
    const int* src_pa = (const int*)d_in[4];
    const int* dst_pa = (const int*)d_in[5];
    const float* Wq_p = (const float*)d_in[6];
    const float* bq_p = (const float*)d_in[7];
    const float* Wk_p = (const float*)d_in[8];
    const float* bk_p = (const float*)d_in[9];
    const float* Wv_p = (const float*)d_in[10];
    const float* bv_p = (const float*)d_in[11];
    const float* Wa_p = (const float*)d_in[12];
    const float* ba_p = (const float*)d_in[13];
    const float* skip_p = (const float*)d_in[14];
    const float* Wq_a = (const float*)d_in[15];
    const float* bq_a = (const float*)d_in[16];
    const float* Wk_a = (const float*)d_in[17];
    const float* bk_a = (const float*)d_in[18];
    const float* Wv_a = (const float*)d_in[19];
    const float* bv_a = (const float*)d_in[20];
    const float* Wa_a = (const float*)d_in[21];
    const float* ba_a = (const float*)d_in[22];
    const float* skip_a = (const float*)d_in[23];
    const float* a_rel_ap = (const float*)d_in[24];
    const float* m_rel_ap = (const float*)d_in[25];
    const float* p_rel_ap = (const float*)d_in[26];
    const float* a_rel_pa = (const float*)d_in[27];
    const float* m_rel_pa = (const float*)d_in[28];
    const float* p_rel_pa = (const float*)d_in[29];
    float* out = (float*)d_out;

    int E_ap = in_sizes[2];
    int E_pa = in_sizes[4];

    float *Wk_ap, *Wv_ap, *Wk_pa, *Wv_pa, *bk_ap, *bv_ap, *bk_pa, *bv_pa;
    float *q_p, *q_a, *kv_ap, *kv_pa, *agg_p, *agg_a;
    int *cnt_p, *cnt_a, *off_p, *off_a, *cur_p, *cur_a, *esrc_p, *esrc_a, *partials;
    cudaGetSymbolAddress((void**)&Wk_ap, g_Wk_ap);
    cudaGetSymbolAddress((void**)&Wv_ap, g_Wv_ap);
    cudaGetSymbolAddress((void**)&Wk_pa, g_Wk_pa);
    cudaGetSymbolAddress((void**)&Wv_pa, g_Wv_pa);
    cudaGetSymbolAddress((void**)&bk_ap, g_bk_ap);
    cudaGetSymbolAddress((void**)&bv_ap, g_bv_ap);
    cudaGetSymbolAddress((void**)&bk_pa, g_bk_pa);
    cudaGetSymbolAddress((void**)&bv_pa, g_bv_pa);
    cudaGetSymbolAddress((void**)&q_p, g_q_p);
    cudaGetSymbolAddress((void**)&q_a, g_q_a);
    cudaGetSymbolAddress((void**)&kv_ap, g_kv_ap);
    cudaGetSymbolAddress((void**)&kv_pa, g_kv_pa);
    cudaGetSymbolAddress((void**)&agg_p, g_agg_p);
    cudaGetSymbolAddress((void**)&agg_a, g_agg_a);
    cudaGetSymbolAddress((void**)&cnt_p, g_cnt_p);
    cudaGetSymbolAddress((void**)&cnt_a, g_cnt_a);
    cudaGetSymbolAddress((void**)&off_p, g_off_p);
    cudaGetSymbolAddress((void**)&off_a, g_off_a);
    cudaGetSymbolAddress((void**)&cur_p, g_cur_p);
    cudaGetSymbolAddress((void**)&cur_a, g_cur_a);
    cudaGetSymbolAddress((void**)&esrc_p, g_esrc_p);
    cudaGetSymbolAddress((void**)&esrc_a, g_esrc_a);
    cudaGetSymbolAddress((void**)&partials, g_partials);

    const int SMEM = 2 * DMODEL * DMODEL * (int)sizeof(float);  // 128 KB
    cudaFuncSetAttribute(gemm_qkv3, cudaFuncAttributeMaxDynamicSharedMemorySize, SMEM);
    cudaFuncSetAttribute(gemm_out, cudaFuncAttributeMaxDynamicSharedMemorySize, SMEM);

    // weight folding
    FuseArgs fa;
    fa.W[0] = Wk_a; fa.b[0] = bk_a; fa.rel[0] = a_rel_ap; fa.We[0] = Wk_ap; fa.be[0] = bk_ap;
    fa.W[1] = Wv_a; fa.b[1] = bv_a; fa.rel[1] = m_rel_ap; fa.We[1] = Wv_ap; fa.be[1] = bv_ap;
    fa.W[2] = Wk_p; fa.b[2] = bk_p; fa.rel[2] = a_rel_pa; fa.We[2] = Wk_pa; fa.be[2] = bk_pa;
    fa.W[3] = Wv_p; fa.b[3] = bv_p; fa.rel[3] = m_rel_pa; fa.We[3] = Wv_pa; fa.be[3] = bv_pa;
    fuse_all<<<dim3(DMODEL, 4), DMODEL>>>(fa);

    // CSR build
    fill_cnt<<<256, 256>>>(cnt_p, NP, cnt_a, NA);
    hist2<<<2048, 256>>>(dst_ap, E_ap, cnt_p, dst_pa, E_pa, cnt_a);
    scan_local<<<NBP + NBA, 1024>>>(cnt_p, cnt_a, off_p, off_a, partials);
    scan_partials<<<1, 32>>>(partials, off_p, off_a);
    add_base<<<NBP + NBA, 1024>>>(off_p, off_a, cur_p, cur_a, partials);
    build_esrc<<<2048, 256>>>(src_ap, dst_ap, E_ap, cur_p, esrc_p,
                              src_pa, dst_pa, E_pa, cur_a, esrc_a);

    // QKV projections (q pre-scaled, K|V interleaved)
    int gb_p = (NP + DMODEL - 1) / DMODEL;
    int gb_a = (NA + DMODEL - 1) / DMODEL;
    gemm_qkv3<<<gb_a, 256, SMEM>>>(x_a,
                                   Wq_a, bq_a, q_a, DMODEL, p_rel_pa,
                                   Wk_ap, bk_ap, kv_ap, KVLD,
                                   Wv_ap, bv_ap, kv_ap + DMODEL, KVLD, NA);
    gemm_qkv3<<<gb_p, 256, SMEM>>>(x_p,
                                   Wq_p, bq_p, q_p, DMODEL, p_rel_ap,
                                   Wk_pa, bk_pa, kv_pa, KVLD,
                                   Wv_pa, bv_pa, kv_pa + DMODEL, KVLD, NP);

    // fused per-dst attention (atomic-free, normalized)
    node_attn<<<(NP * 32 + 255) / 256, 256>>>(q_p, kv_ap, off_p, esrc_p, agg_p, NP);
    node_attn<<<(NA * 32 + 255) / 256, 256>>>(q_a, kv_pa, off_a, esrc_a, agg_a, NA);

    // output projections + skip blend
    gemm_out<<<gb_p, 256, SMEM>>>(agg_p, Wa_p, ba_p, skip_p, x_p, out, NP);
    gemm_out<<<gb_a, 256, SMEM>>>(agg_a, Wa_a, ba_a, skip_a, x_a,
                                  out + (size_t)NP * DMODEL, NA);
}

// round 6
// speedup vs baseline: 1.4382x; 1.2021x over previous
#include <cuda_runtime.h>
#include <cuda_bf16.h>
#include <math.h>
#include <stdint.h>

#define NP 100000
#define NA 50000
#define EMAX 500000
#define DMODEL 128
#define NH 8
#define HDIM 16
#define KVLD 256    // interleaved K|V row stride

#define WWORDS 192  // 384 bf16 (K_ext) per row = 192 u32 words
#define AK 196      // smem row stride in words (padding: stride%32 == 4 -> conflict-free frags)

#define SCAN_E 4096
#define NBP ((NP + SCAN_E - 1) / SCAN_E)
#define NBA ((NA + SCAN_E - 1) / SCAN_E)

// ---------------- scratch (device globals; no allocation allowed) ----------------
__device__ float g_Wk_ap[DMODEL * DMODEL];
__device__ float g_Wv_ap[DMODEL * DMODEL];
__device__ float g_Wk_pa[DMODEL * DMODEL];
__device__ float g_Wv_pa[DMODEL * DMODEL];
__device__ float g_bk_ap[DMODEL];
__device__ float g_bv_ap[DMODEL];
__device__ float g_bk_pa[DMODEL];
__device__ float g_bv_pa[DMODEL];

// bf16-split packed weights: [matrix][n][192 words]; slot seq per k: (HI,HI,LO)
__device__ uint32_t g_wext[8][DMODEL * WWORDS];

__device__ float g_q_p[(size_t)NP * DMODEL];     // pre-scaled by p_rel_ap/4
__device__ float g_q_a[(size_t)NA * DMODEL];     // pre-scaled by p_rel_pa/4
__device__ float g_kv_ap[(size_t)NA * KVLD];
__device__ float g_kv_pa[(size_t)NP * KVLD];

__device__ int g_cnt_p[NP];
__device__ int g_cnt_a[NA];
__device__ int g_off_p[NP + 1];
__device__ int g_off_a[NA + 1];
__device__ int g_cur_p[NP];
__device__ int g_cur_a[NA];
__device__ int g_partials[NBP + NBA];
__device__ int g_esrc_p[EMAX];
__device__ int g_esrc_a[EMAX];

__device__ float g_agg_p[(size_t)NP * DMODEL];
__device__ float g_agg_a[(size_t)NA * DMODEL];

// ---------------- bf16 split helpers ----------------
__device__ __forceinline__ void bsplit(float x, uint16_t& h, uint16_t& l) {
    __nv_bfloat16 hb = __float2bfloat16(x);
    float r = x - __bfloat162float(hb);
    __nv_bfloat16 lb = __float2bfloat16(r);
    h = __bfloat16_as_ushort(hb);
    l = __bfloat16_as_ushort(lb);
}
__device__ __forceinline__ uint32_t pk(uint16_t lo16, uint16_t hi16) {
    return (uint32_t)lo16 | ((uint32_t)hi16 << 16);
}

// ---------------- mma.m16n8k16 bf16 wrapper ----------------
__device__ __forceinline__ void mma16816(float* c, const uint32_t* a,
                                         uint32_t b0, uint32_t b1) {
    asm("mma.sync.aligned.m16n8k16.row.col.f32.bf16.bf16.f32 "
        "{%0,%1,%2,%3}, {%4,%5,%6,%7}, {%8,%9}, {%0,%1,%2,%3};"
        : "+f"(c[0]), "+f"(c[1]), "+f"(c[2]), "+f"(c[3])
        : "r"(a[0]), "r"(a[1]), "r"(a[2]), "r"(a[3]), "r"(b0), "r"(b1));
}

// ---------------- setup kernels ----------------
struct FuseArgs {
    const float* W[4];
    const float* b[4];
    const float* rel[4];
    float* We[4];
    float* be[4];
};

__global__ void fuse_all(FuseArgs a) {
    int m = blockIdx.y;
    int k = blockIdx.x;
    int tid = threadIdx.x;
    int h = tid >> 4;
    int e = tid & 15;
    const float* r = a.rel[m] + h * HDIM * HDIM;
    const float* wrow = a.W[m] + k * DMODEL + h * HDIM;
    float s = 0.0f;
#pragma unroll
    for (int d = 0; d < HDIM; d++) s += wrow[d] * r[d * HDIM + e];
    a.We[m][k * DMODEL + tid] = s;
    if (k == 0) {
        const float* bb = a.b[m] + h * HDIM;
        float sb = 0.0f;
#pragma unroll
        for (int d = 0; d < HDIM; d++) sb += bb[d] * r[d * HDIM + e];
        a.be[m][tid] = sb;
    }
}

// split+pack all 8 weight matrices into g_wext (B-side slot order HI,HI,LO)
struct ConvArgs { const float* W[8]; };
__global__ void convert_w(ConvArgs ca) {
    int m = blockIdx.y;          // matrix
    int n = blockIdx.x;          // output column 0..127
    int t = threadIdx.x;         // k-pair 0..63
    const float* W = ca.W[m];
    float w0 = W[(2 * t) * DMODEL + n];
    float w1 = W[(2 * t + 1) * DMODEL + n];
    uint16_t h0, l0, h1, l1;
    bsplit(w0, h0, l0);
    bsplit(w1, h1, l1);
    uint32_t* dst = g_wext[m] + n * WWORDS + t * 3;
    dst[0] = pk(h0, h0);
    dst[1] = pk(l0, h1);
    dst[2] = pk(h1, l1);
}

__global__ void fill_cnt(int* __restrict__ c0, int n0, int* __restrict__ c1, int n1) {
    int i = blockIdx.x * blockDim.x + threadIdx.x;
    int stride = gridDim.x * blockDim.x;
    for (; i < n0 + n1; i += stride) {
        if (i < n0) c0[i] = 0;
        else c1[i - n0] = 0;
    }
}

__global__ void hist2(const int* __restrict__ d0, int E0, int* __restrict__ c0,
                      const int* __restrict__ d1, int E1, int* __restrict__ c1) {
    int i = blockIdx.x * blockDim.x + threadIdx.x;
    int stride = gridDim.x * blockDim.x;
    for (; i < E0 + E1; i += stride) {
        if (i < E0) atomicAdd(&c0[d0[i]], 1);
        else atomicAdd(&c1[d1[i - E0]], 1);
    }
}

__global__ __launch_bounds__(1024) void scan_local(
        const int* __restrict__ cnt_p, const int* __restrict__ cnt_a,
        int* __restrict__ off_p, int* __restrict__ off_a,
        int* __restrict__ partials) {
    __shared__ int wsum[32];
    int b = blockIdx.x;
    const int* cnt;
    int* off;
    int n, base;
    if (b < NBP) { cnt = cnt_p; off = off_p; n = NP; base = b * SCAN_E; }
    else { cnt = cnt_a; off = off_a; n = NA; base = (b - NBP) * SCAN_E; }
    int tid = threadIdx.x;
    int lane = tid & 31;
    int wid = tid >> 5;
    int i = base + tid * 4;

    int4 v = make_int4(0, 0, 0, 0);
    if (i < n) v = *(const int4*)&cnt[i];
    int s0 = v.x;
    int s1 = s0 + v.y;
    int s2 = s1 + v.z;
    int s3 = s2 + v.w;
    int x = s3;
#pragma unroll
    for (int d = 1; d < 32; d <<= 1) {
        int t = __shfl_up_sync(0xffffffffu, x, d);
        if (lane >= d) x += t;
    }
    if (lane == 31) wsum[wid] = x;
    __syncthreads();
    if (wid == 0) {
        int s = wsum[lane];
#pragma unroll
        for (int d = 1; d < 32; d <<= 1) {
            int t = __shfl_up_sync(0xffffffffu, s, d);
            if (lane >= d) s += t;
        }
        wsum[lane] = s;
    }
    __syncthreads();
    int excl = (wid ? wsum[wid - 1] : 0) + (x - s3);
    if (i < n) {
        int4 o;
        o.x = excl;
        o.y = excl + s0;
        o.z = excl + s1;
        o.w = excl + s2;
        *(int4*)&off[i] = o;
    }
    if (tid == 0) partials[b] = wsum[31];
}

__global__ void scan_partials(int* __restrict__ partials,
                              int* __restrict__ off_p, int* __restrict__ off_a) {
    if (threadIdx.x == 0) {
        int run = 0;
        for (int b = 0; b < NBP; b++) {
            int t = partials[b];
            partials[b] = run;
            run += t;
        }
        off_p[NP] = run;
        run = 0;
        for (int b = NBP; b < NBP + NBA; b++) {
            int t = partials[b];
            partials[b] = run;
            run += t;
        }
        off_a[NA] = run;
    }
}

__global__ __launch_bounds__(1024) void add_base(
        int* __restrict__ off_p, int* __restrict__ off_a,
        int* __restrict__ cur_p, int* __restrict__ cur_a,
        const int* __restrict__ partials) {
    int b = blockIdx.x;
    int* off;
    int* cur;
    int n, base;
    if (b < NBP) { off = off_p; cur = cur_p; n = NP; base = b * SCAN_E; }
    else { off = off_a; cur = cur_a; n = NA; base = (b - NBP) * SCAN_E; }
    int add = partials[b];
    int i = base + threadIdx.x * 4;
    if (i < n) {
        int4 o = *(const int4*)&off[i];
        o.x += add; o.y += add; o.z += add; o.w += add;
        *(int4*)&off[i] = o;
        *(int4*)&cur[i] = o;
    }
}

__global__ void build_esrc(const int* __restrict__ src0, const int* __restrict__ dst0,
                           int E0, int* __restrict__ cur0, int* __restrict__ out0,
                           const int* __restrict__ src1, const int* __restrict__ dst1,
                           int E1, int* __restrict__ cur1, int* __restrict__ out1) {
    int i = blockIdx.x * blockDim.x + threadIdx.x;
    int stride = gridDim.x * blockDim.x;
    for (; i < E0 + E1; i += stride) {
        if (i < E0) {
            int pos = atomicAdd(&cur0[dst0[i]], 1);
            out0[pos] = src0[i];
        } else {
            int j = i - E0;
            int pos = atomicAdd(&cur1[dst1[j]], 1);
            out1[pos] = src1[j];
        }
    }
}

// ---------------- tensor-core GEMM pieces ----------------
// Fill A_ext smem from fp32 X tile: slot seq per k: (hi, lo, hi).
__device__ __forceinline__ void fill_Aext(const float* __restrict__ X, int N, int row0,
                                          uint32_t* As, int tid) {
    const float4* Xg = (const float4*)X;
#pragma unroll
    for (int i = tid; i < DMODEL * 32; i += 256) {
        int r = i >> 5;
        int c = i & 31;
        int gr = row0 + r;
        float4 v = make_float4(0.f, 0.f, 0.f, 0.f);
        if (gr < N) v = Xg[(size_t)gr * 32 + c];
        uint16_t h0, l0, h1, l1, h2, l2, h3, l3;
        bsplit(v.x, h0, l0);
        bsplit(v.y, h1, l1);
        bsplit(v.z, h2, l2);
        bsplit(v.w, h3, l3);
        uint32_t* dst = As + r * AK + c * 6;
        // k-pair (v.x, v.y): words (h0,l0)(h0,h1)(l1,h1)
        ((uint2*)dst)[0] = make_uint2(pk(h0, l0), pk(h0, h1));
        ((uint2*)dst)[1] = make_uint2(pk(l1, h1), pk(h2, l2));
        ((uint2*)dst)[2] = make_uint2(pk(h2, h3), pk(l3, h3));
    }
}

__device__ __forceinline__ void fill_Bext(const uint32_t* __restrict__ Wext,
                                          uint32_t* Bs, int tid) {
    const uint4* src = (const uint4*)Wext;
#pragma unroll
    for (int i = tid; i < DMODEL * WWORDS / 4; i += 256) {
        int n = i / (WWORDS / 4);
        int w = i % (WWORDS / 4);
        *(uint4*)&Bs[n * AK + w * 4] = src[i];
    }
}

// core mma over K_ext=384: warp tile m32 x n64, returns acc[2][8][4]
__device__ __forceinline__ void mm_mma(const uint32_t* As, const uint32_t* Bs,
                                       int mrow, int ncol, int g, int tig,
                                       float acc[2][8][4]) {
#pragma unroll
    for (int mi = 0; mi < 2; mi++)
#pragma unroll
        for (int ni = 0; ni < 8; ni++)
#pragma unroll
            for (int j = 0; j < 4; j++) acc[mi][ni][j] = 0.0f;

#pragma unroll 1
    for (int kc = 0; kc < 24; kc++) {
        int kw = kc * 8 + tig;
        uint32_t a[2][4];
#pragma unroll
        for (int mi = 0; mi < 2; mi++) {
            int r = mrow + mi * 16 + g;
            a[mi][0] = As[r * AK + kw];
            a[mi][1] = As[(r + 8) * AK + kw];
            a[mi][2] = As[r * AK + kw + 4];
            a[mi][3] = As[(r + 8) * AK + kw + 4];
        }
#pragma unroll
        for (int ni = 0; ni < 8; ni++) {
            int n = ncol + ni * 8 + g;
            uint32_t b0 = Bs[n * AK + kw];
            uint32_t b1 = Bs[n * AK + kw + 4];
            mma16816(acc[0][ni], a[0], b0, b1);
            mma16816(acc[1][ni], a[1], b0, b1);
        }
    }
}

// ---------------- fused Q/K/V projection (tensor core) ----------------
__global__ __launch_bounds__(256) void gemm_qkv3(
        const float* __restrict__ X,
        const uint32_t* __restrict__ We0, const float* __restrict__ b0,
        float* __restrict__ Y0, int ld0, const float* __restrict__ prel,
        const uint32_t* __restrict__ We1, const float* __restrict__ b1,
        float* __restrict__ Y1, int ld1,
        const uint32_t* __restrict__ We2, const float* __restrict__ b2,
        float* __restrict__ Y2, int ld2,
        int N) {
    extern __shared__ uint32_t smu[];
    uint32_t* As = smu;
    uint32_t* Bs = smu + DMODEL * AK;
    int tid = threadIdx.x;
    int row0 = blockIdx.x * DMODEL;
    int w = tid >> 5, lane = tid & 31;
    int g = lane >> 2, tig = lane & 3;
    int mrow = (w & 3) * 32;
    int ncol = (w >> 2) * 64;

    fill_Aext(X, N, row0, As, tid);

    const uint32_t* Wm[3] = {We0, We1, We2};
    const float* bm[3] = {b0, b1, b2};
    float* Ym[3] = {Y0, Y1, Y2};
    int ldm[3] = {ld0, ld1, ld2};

#pragma unroll 1
    for (int m = 0; m < 3; m++) {
        fill_Bext(Wm[m], Bs, tid);
        __syncthreads();

        float acc[2][8][4];
        mm_mma(As, Bs, mrow, ncol, g, tig, acc);

        const float* bias = bm[m];
        float* Y = Ym[m];
        int ld = ldm[m];
#pragma unroll
        for (int mi = 0; mi < 2; mi++) {
            int r0 = row0 + mrow + mi * 16 + g;
#pragma unroll
            for (int ni = 0; ni < 8; ni++) {
                int col = ncol + ni * 8 + 2 * tig;
                float sc = (m == 0) ? __ldg(&prel[col >> 4]) * 0.25f : 1.0f;
                float bvx = bias[col], bvy = bias[col + 1];
                float* a4 = acc[mi][ni];
                if (r0 < N) {
                    float2 o;
                    o.x = (a4[0] + bvx) * sc;
                    o.y = (a4[1] + bvy) * sc;
                    *(float2*)&Y[(size_t)r0 * ld + col] = o;
                }
                if (r0 + 8 < N) {
                    float2 o;
                    o.x = (a4[2] + bvx) * sc;
                    o.y = (a4[3] + bvy) * sc;
                    *(float2*)&Y[(size_t)(r0 + 8) * ld + col] = o;
                }
            }
        }
        __syncthreads();
    }
}

// ---------------- output GEMM: Y = al*(agg @ W + b) + (1-al)*Xres ----------------
__global__ __launch_bounds__(256) void gemm_out(
        const float* __restrict__ Xagg, const uint32_t* __restrict__ Wext,
        const float* __restrict__ bias,
        const float* __restrict__ skip, const float* __restrict__ Xres,
        float* __restrict__ Y, int N) {
    extern __shared__ uint32_t smu[];
    uint32_t* As = smu;
    uint32_t* Bs = smu + DMODEL * AK;
    int tid = threadIdx.x;
    int row0 = blockIdx.x * DMODEL;
    int w = tid >> 5, lane = tid & 31;
    int g = lane >> 2, tig = lane & 3;
    int mrow = (w & 3) * 32;
    int ncol = (w >> 2) * 64;

    fill_Aext(Xagg, N, row0, As, tid);
    fill_Bext(Wext, Bs, tid);
    __syncthreads();

    float acc[2][8][4];
    mm_mma(As, Bs, mrow, ncol, g, tig, acc);

    float al = 1.0f / (1.0f + __expf(-skip[0]));
    float be = 1.0f - al;
#pragma unroll
    for (int mi = 0; mi < 2; mi++) {
        int r0 = row0 + mrow + mi * 16 + g;
#pragma unroll
        for (int ni = 0; ni < 8; ni++) {
            int col = ncol + ni * 8 + 2 * tig;
            float bvx = bias[col], bvy = bias[col + 1];
            float* a4 = acc[mi][ni];
            if (r0 < N) {
                float2 xr = *(const float2*)&Xres[(size_t)r0 * DMODEL + col];
                float2 o;
                o.x = al * (a4[0] + bvx) + be * xr.x;
                o.y = al * (a4[1] + bvy) + be * xr.y;
                *(float2*)&Y[(size_t)r0 * DMODEL + col] = o;
            }
            if (r0 + 8 < N) {
                float2 xr = *(const float2*)&Xres[(size_t)(r0 + 8) * DMODEL + col];
                float2 o;
                o.x = al * (a4[2] + bvx) + be * xr.x;
                o.y = al * (a4[3] + bvy) + be * xr.y;
                *(float2*)&Y[(size_t)(r0 + 8) * DMODEL + col] = o;
            }
        }
    }
}

// ---------------- fused per-dst attention ----------------
__global__ void node_attn(const float* __restrict__ Q, const float* __restrict__ KV,
                          const int* __restrict__ off, const int* __restrict__ esrc,
                          float* __restrict__ agg, int N) {
    int gg = blockIdx.x * blockDim.x + threadIdx.x;
    int w = gg >> 5;
    int lane = gg & 31;
    if (w >= N) return;
    float4 q = ((const float4*)(Q + (size_t)w * DMODEL))[lane];
    int j0 = off[w];
    int j1 = off[w + 1];
    float4 acc = make_float4(0.f, 0.f, 0.f, 0.f);
    float den = 0.0f;
    for (int j = j0; j < j1; j++) {
        int s = __ldg(&esrc[j]);
        const float4* kvrow = (const float4*)(KV + (size_t)s * KVLD);
        float4 k4 = __ldg(&kvrow[lane]);
        float p = k4.x * q.x + k4.y * q.y + k4.z * q.z + k4.w * q.w;
        p += __shfl_xor_sync(0xffffffffu, p, 1);
        p += __shfl_xor_sync(0xffffffffu, p, 2);
        float ev = __expf(p);
        float4 v4 = __ldg(&kvrow[lane + 32]);
        acc.x += ev * v4.x;
        acc.y += ev * v4.y;
        acc.z += ev * v4.z;
        acc.w += ev * v4.w;
        den += ev;
    }
    float inv = 1.0f / (den + 1e-16f);
    float4 o;
    o.x = acc.x * inv;
    o.y = acc.y * inv;
    o.z = acc.z * inv;
    o.w = acc.w * inv;
    ((float4*)(agg + (size_t)w * DMODEL))[lane] = o;
}

// ---------------- launch ----------------
extern "C" void kernel_launch(void* const* d_in, const int* in_sizes, int n_in,
                              void* d_out, int out_size) {
    const float* x_p = (const float*)d_in[0];
    const float* x_a = (const float*)d_in[1];
    const int* src_ap = (const int*)d_in[2];
    const int* dst_ap = (const int*)d_in[3];
    const int* src_pa = (const int*)d_in[4];
    const int* dst_pa = (const int*)d_in[5];
    const float* Wq_p = (const float*)d_in[6];
    const float* bq_p = (const float*)d_in[7];
    const float* Wk_p = (const float*)d_in[8];
    const float* bk_p = (const float*)d_in[9];
    const float* Wv_p = (const float*)d_in[10];
    const float* bv_p = (const float*)d_in[11];
    const float* Wa_p = (const float*)d_in[12];
    const float* ba_p = (const float*)d_in[13];
    const float* skip_p = (const float*)d_in[14];
    const float* Wq_a = (const float*)d_in[15];
    const float* bq_a = (const float*)d_in[16];
    const float* Wk_a = (const float*)d_in[17];
    const float* bk_a = (const float*)d_in[18];
    const float* Wv_a = (const float*)d_in[19];
    const float* bv_a = (const float*)d_in[20];
    const float* Wa_a = (const float*)d_in[21];
    const float* ba_a = (const float*)d_in[22];
    const float* skip_a = (const float*)d_in[23];
    const float* a_rel_ap = (const float*)d_in[24];
    const float* m_rel_ap = (const float*)d_in[25];
    const float* p_rel_ap = (const float*)d_in[26];
    const float* a_rel_pa = (const float*)d_in[27];
    const float* m_rel_pa = (const float*)d_in[28];
    const float* p_rel_pa = (const float*)d_in[29];
    float* out = (float*)d_out;

    int E_ap = in_sizes[2];
    int E_pa = in_sizes[4];

    float *Wk_ap, *Wv_ap, *Wk_pa, *Wv_pa, *bk_ap, *bv_ap, *bk_pa, *bv_pa;
    float *q_p, *q_a, *kv_ap, *kv_pa, *agg_p, *agg_a;
    uint32_t* wext;
    int *cnt_p, *cnt_a, *off_p, *off_a, *cur_p, *cur_a, *esrc_p, *esrc_a, *partials;
    cudaGetSymbolAddress((void**)&Wk_ap, g_Wk_ap);
    cudaGetSymbolAddress((void**)&Wv_ap, g_Wv_ap);
    cudaGetSymbolAddress((void**)&Wk_pa, g_Wk_pa);
    cudaGetSymbolAddress((void**)&Wv_pa, g_Wv_pa);
    cudaGetSymbolAddress((void**)&bk_ap, g_bk_ap);
    cudaGetSymbolAddress((void**)&bv_ap, g_bv_ap);
    cudaGetSymbolAddress((void**)&bk_pa, g_bk_pa);
    cudaGetSymbolAddress((void**)&bv_pa, g_bv_pa);
    cudaGetSymbolAddress((void**)&wext, g_wext);
    cudaGetSymbolAddress((void**)&q_p, g_q_p);
    cudaGetSymbolAddress((void**)&q_a, g_q_a);
    cudaGetSymbolAddress((void**)&kv_ap, g_kv_ap);
    cudaGetSymbolAddress((void**)&kv_pa, g_kv_pa);
    cudaGetSymbolAddress((void**)&agg_p, g_agg_p);
    cudaGetSymbolAddress((void**)&agg_a, g_agg_a);
    cudaGetSymbolAddress((void**)&cnt_p, g_cnt_p);
    cudaGetSymbolAddress((void**)&cnt_a, g_cnt_a);
    cudaGetSymbolAddress((void**)&off_p, g_off_p);
    cudaGetSymbolAddress((void**)&off_a, g_off_a);
    cudaGetSymbolAddress((void**)&cur_p, g_cur_p);
    cudaGetSymbolAddress((void**)&cur_a, g_cur_a);
    cudaGetSymbolAddress((void**)&esrc_p, g_esrc_p);
    cudaGetSymbolAddress((void**)&esrc_a, g_esrc_a);
    cudaGetSymbolAddress((void**)&partials, g_partials);

    const int SMEM = 2 * DMODEL * AK * (int)sizeof(uint32_t);  // 200704 B
    cudaFuncSetAttribute(gemm_qkv3, cudaFuncAttributeMaxDynamicSharedMemorySize, SMEM);
    cudaFuncSetAttribute(gemm_out, cudaFuncAttributeMaxDynamicSharedMemorySize, SMEM);

    // weight folding (fused K/V matrices)
    FuseArgs fa;
    fa.W[0] = Wk_a; fa.b[0] = bk_a; fa.rel[0] = a_rel_ap; fa.We[0] = Wk_ap; fa.be[0] = bk_ap;
    fa.W[1] = Wv_a; fa.b[1] = bv_a; fa.rel[1] = m_rel_ap; fa.We[1] = Wv_ap; fa.be[1] = bv_ap;
    fa.W[2] = Wk_p; fa.b[2] = bk_p; fa.rel[2] = a_rel_pa; fa.We[2] = Wk_pa; fa.be[2] = bk_pa;
    fa.W[3] = Wv_p; fa.b[3] = bv_p; fa.rel[3] = m_rel_pa; fa.We[3] = Wv_pa; fa.be[3] = bv_pa;
    fuse_all<<<dim3(DMODEL, 4), DMODEL>>>(fa);

    // bf16-split + pack all 8 weight matrices
    ConvArgs ca;
    ca.W[0] = Wq_p;  ca.W[1] = Wk_pa; ca.W[2] = Wv_pa;
    ca.W[3] = Wq_a;  ca.W[4] = Wk_ap; ca.W[5] = Wv_ap;
    ca.W[6] = Wa_p;  ca.W[7] = Wa_a;
    convert_w<<<dim3(DMODEL, 8), 64>>>(ca);

    // CSR build
    fill_cnt<<<256, 256>>>(cnt_p, NP, cnt_a, NA);
    hist2<<<2048, 256>>>(dst_ap, E_ap, cnt_p, dst_pa, E_pa, cnt_a);
    scan_local<<<NBP + NBA, 1024>>>(cnt_p, cnt_a, off_p, off_a, partials);
    scan_partials<<<1, 32>>>(partials, off_p, off_a);
    add_base<<<NBP + NBA, 1024>>>(off_p, off_a, cur_p, cur_a, partials);
    build_esrc<<<2048, 256>>>(src_ap, dst_ap, E_ap, cur_p, esrc_p,
                              src_pa, dst_pa, E_pa, cur_a, esrc_a);

    // QKV projections (tensor core; q pre-scaled, K|V interleaved)
    int gb_p = (NP + DMODEL - 1) / DMODEL;
    int gb_a = (NA + DMODEL - 1) / DMODEL;
    gemm_qkv3<<<gb_a, 256, SMEM>>>(x_a,
                                   wext + 3 * DMODEL * WWORDS, bq_a, q_a, DMODEL, p_rel_pa,
                                   wext + 4 * DMODEL * WWORDS, bk_ap, kv_ap, KVLD,
                                   wext + 5 * DMODEL * WWORDS, bv_ap, kv_ap + DMODEL, KVLD,
                                   NA);
    gemm_qkv3<<<gb_p, 256, SMEM>>>(x_p,
                                   wext + 0 * DMODEL * WWORDS, bq_p, q_p, DMODEL, p_rel_ap,
                                   wext + 1 * DMODEL * WWORDS, bk_pa, kv_pa, KVLD,
                                   wext + 2 * DMODEL * WWORDS, bv_pa, kv_pa + DMODEL, KVLD,
                                   NP);

    // fused per-dst attention (atomic-free, normalized)
    node_attn<<<(NP * 32 + 255) / 256, 256>>>(q_p, kv_ap, off_p, esrc_p, agg_p, NP);
    node_attn<<<(NA * 32 + 255) / 256, 256>>>(q_a, kv_pa, off_a, esrc_a, agg_a, NA);

    // output projections + skip blend
    gemm_out<<<gb_p, 256, SMEM>>>(agg_p, wext + 6 * DMODEL * WWORDS, ba_p, skip_p,
                                  x_p, out, NP);
    gemm_out<<<gb_a, 256, SMEM>>>(agg_a, wext + 7 * DMODEL * WWORDS, ba_a, skip_a,
                                  x_a, out + (size_t)NP * DMODEL, NA);
}

// round 7
// speedup vs baseline: 1.5635x; 1.0871x over previous
#include <cuda_runtime.h>
#include <cuda_bf16.h>
#include <math.h>
#include <stdint.h>

#define NP 100000
#define NA 50000
#define EMAX 500000
#define DMODEL 128
#define NH 8
#define HDIM 16
#define KVLD 256    // interleaved K|V row stride

#define WWORDS 192  // 384 bf16 (K_ext) per row = 192 u32 words
#define AK 196      // smem row stride in words (conflict-free fragment loads)

#define SCAN_E 4096
#define NBP ((NP + SCAN_E - 1) / SCAN_E)
#define NBA ((NA + SCAN_E - 1) / SCAN_E)

// ---------------- scratch (device globals; no allocation allowed) ----------------
__device__ float g_Wk_ap[DMODEL * DMODEL];
__device__ float g_Wv_ap[DMODEL * DMODEL];
__device__ float g_Wk_pa[DMODEL * DMODEL];
__device__ float g_Wv_pa[DMODEL * DMODEL];
__device__ float g_bk_ap[DMODEL];
__device__ float g_bv_ap[DMODEL];
__device__ float g_bk_pa[DMODEL];
__device__ float g_bv_pa[DMODEL];

__device__ uint32_t g_wext[8][DMODEL * WWORDS];

__device__ float g_q_p[(size_t)NP * DMODEL];
__device__ float g_q_a[(size_t)NA * DMODEL];
__device__ float g_kv_ap[(size_t)NA * KVLD];
__device__ float g_kv_pa[(size_t)NP * KVLD];

__device__ int g_cnt_p[NP];
__device__ int g_cnt_a[NA];
__device__ int g_off_p[NP + 1];
__device__ int g_off_a[NA + 1];
__device__ int g_cur_p[NP];
__device__ int g_cur_a[NA];
__device__ int g_partials[NBP + NBA];
__device__ int g_esrc_p[EMAX];
__device__ int g_esrc_a[EMAX];

__device__ float g_agg_p[(size_t)NP * DMODEL];
__device__ float g_agg_a[(size_t)NA * DMODEL];

// ---------------- bf16 split helpers ----------------
__device__ __forceinline__ void bsplit(float x, uint16_t& h, uint16_t& l) {
    __nv_bfloat16 hb = __float2bfloat16(x);
    float r = x - __bfloat162float(hb);
    __nv_bfloat16 lb = __float2bfloat16(r);
    h = __bfloat16_as_ushort(hb);
    l = __bfloat16_as_ushort(lb);
}
__device__ __forceinline__ uint32_t pk(uint16_t lo16, uint16_t hi16) {
    return (uint32_t)lo16 | ((uint32_t)hi16 << 16);
}

__device__ __forceinline__ void mma16816(float* c, const uint32_t* a,
                                         uint32_t b0, uint32_t b1) {
    asm("mma.sync.aligned.m16n8k16.row.col.f32.bf16.bf16.f32 "
        "{%0,%1,%2,%3}, {%4,%5,%6,%7}, {%8,%9}, {%0,%1,%2,%3};"
        : "+f"(c[0]), "+f"(c[1]), "+f"(c[2]), "+f"(c[3])
        : "r"(a[0]), "r"(a[1]), "r"(a[2]), "r"(a[3]), "r"(b0), "r"(b1));
}

// ---------------- setup kernels ----------------
struct FuseArgs {
    const float* W[4];
    const float* b[4];
    const float* rel[4];
    float* We[4];
    float* be[4];
};

__global__ void fuse_all(FuseArgs a) {
    int m = blockIdx.y;
    int k = blockIdx.x;
    int tid = threadIdx.x;
    int h = tid >> 4;
    int e = tid & 15;
    const float* r = a.rel[m] + h * HDIM * HDIM;
    const float* wrow = a.W[m] + k * DMODEL + h * HDIM;
    float s = 0.0f;
#pragma unroll
    for (int d = 0; d < HDIM; d++) s += wrow[d] * r[d * HDIM + e];
    a.We[m][k * DMODEL + tid] = s;
    if (k == 0) {
        const float* bb = a.b[m] + h * HDIM;
        float sb = 0.0f;
#pragma unroll
        for (int d = 0; d < HDIM; d++) sb += bb[d] * r[d * HDIM + e];
        a.be[m][tid] = sb;
    }
}

struct ConvArgs { const float* W[8]; };
__global__ void convert_w(ConvArgs ca) {
    int m = blockIdx.y;
    int n = blockIdx.x;
    int t = threadIdx.x;
    const float* W = ca.W[m];
    float w0 = W[(2 * t) * DMODEL + n];
    float w1 = W[(2 * t + 1) * DMODEL + n];
    uint16_t h0, l0, h1, l1;
    bsplit(w0, h0, l0);
    bsplit(w1, h1, l1);
    uint32_t* dst = g_wext[m] + n * WWORDS + t * 3;
    dst[0] = pk(h0, h0);
    dst[1] = pk(l0, h1);
    dst[2] = pk(h1, l1);
}

__global__ void fill_cnt(int* __restrict__ c0, int n0, int* __restrict__ c1, int n1) {
    int i = blockIdx.x * blockDim.x + threadIdx.x;
    int stride = gridDim.x * blockDim.x;
    for (; i < n0 + n1; i += stride) {
        if (i < n0) c0[i] = 0;
        else c1[i - n0] = 0;
    }
}

__global__ void hist2(const int* __restrict__ d0, int E0, int* __restrict__ c0,
                      const int* __restrict__ d1, int E1, int* __restrict__ c1) {
    int i = blockIdx.x * blockDim.x + threadIdx.x;
    int stride = gridDim.x * blockDim.x;
    for (; i < E0 + E1; i += stride) {
        if (i < E0) atomicAdd(&c0[d0[i]], 1);
        else atomicAdd(&c1[d1[i - E0]], 1);
    }
}

__global__ __launch_bounds__(1024) void scan_local(
        const int* __restrict__ cnt_p, const int* __restrict__ cnt_a,
        int* __restrict__ off_p, int* __restrict__ off_a,
        int* __restrict__ partials) {
    __shared__ int wsum[32];
    int b = blockIdx.x;
    const int* cnt;
    int* off;
    int n, base;
    if (b < NBP) { cnt = cnt_p; off = off_p; n = NP; base = b * SCAN_E; }
    else { cnt = cnt_a; off = off_a; n = NA; base = (b - NBP) * SCAN_E; }
    int tid = threadIdx.x;
    int lane = tid & 31;
    int wid = tid >> 5;
    int i = base + tid * 4;

    int4 v = make_int4(0, 0, 0, 0);
    if (i < n) v = *(const int4*)&cnt[i];
    int s0 = v.x;
    int s1 = s0 + v.y;
    int s2 = s1 + v.z;
    int s3 = s2 + v.w;
    int x = s3;
#pragma unroll
    for (int d = 1; d < 32; d <<= 1) {
        int t = __shfl_up_sync(0xffffffffu, x, d);
        if (lane >= d) x += t;
    }
    if (lane == 31) wsum[wid] = x;
    __syncthreads();
    if (wid == 0) {
        int s = wsum[lane];
#pragma unroll
        for (int d = 1; d < 32; d <<= 1) {
            int t = __shfl_up_sync(0xffffffffu, s, d);
            if (lane >= d) s += t;
        }
        wsum[lane] = s;
    }
    __syncthreads();
    int excl = (wid ? wsum[wid - 1] : 0) + (x - s3);
    if (i < n) {
        int4 o;
        o.x = excl;
        o.y = excl + s0;
        o.z = excl + s1;
        o.w = excl + s2;
        *(int4*)&off[i] = o;
    }
    if (tid == 0) partials[b] = wsum[31];
}

__global__ void scan_partials(int* __restrict__ partials,
                              int* __restrict__ off_p, int* __restrict__ off_a) {
    if (threadIdx.x == 0) {
        int run = 0;
        for (int b = 0; b < NBP; b++) {
            int t = partials[b];
            partials[b] = run;
            run += t;
        }
        off_p[NP] = run;
        run = 0;
        for (int b = NBP; b < NBP + NBA; b++) {
            int t = partials[b];
            partials[b] = run;
            run += t;
        }
        off_a[NA] = run;
    }
}

__global__ __launch_bounds__(1024) void add_base(
        int* __restrict__ off_p, int* __restrict__ off_a,
        int* __restrict__ cur_p, int* __restrict__ cur_a,
        const int* __restrict__ partials) {
    int b = blockIdx.x;
    int* off;
    int* cur;
    int n, base;
    if (b < NBP) { off = off_p; cur = cur_p; n = NP; base = b * SCAN_E; }
    else { off = off_a; cur = cur_a; n = NA; base = (b - NBP) * SCAN_E; }
    int add = partials[b];
    int i = base + threadIdx.x * 4;
    if (i < n) {
        int4 o = *(const int4*)&off[i];
        o.x += add; o.y += add; o.z += add; o.w += add;
        *(int4*)&off[i] = o;
        *(int4*)&cur[i] = o;
    }
}

__global__ void build_esrc(const int* __restrict__ src0, const int* __restrict__ dst0,
                           int E0, int* __restrict__ cur0, int* __restrict__ out0,
                           const int* __restrict__ src1, const int* __restrict__ dst1,
                           int E1, int* __restrict__ cur1, int* __restrict__ out1) {
    int i = blockIdx.x * blockDim.x + threadIdx.x;
    int stride = gridDim.x * blockDim.x;
    for (; i < E0 + E1; i += stride) {
        if (i < E0) {
            int pos = atomicAdd(&cur0[dst0[i]], 1);
            out0[pos] = src0[i];
        } else {
            int j = i - E0;
            int pos = atomicAdd(&cur1[dst1[j]], 1);
            out1[pos] = src1[j];
        }
    }
}

// ---------------- tensor-core GEMM pieces ----------------
__device__ __forceinline__ void fill_Aext(const float* __restrict__ X, int N, int row0,
                                          uint32_t* As, int tid) {
    const float4* Xg = (const float4*)X;
#pragma unroll
    for (int i = tid; i < DMODEL * 32; i += 256) {
        int r = i >> 5;
        int c = i & 31;
        int gr = row0 + r;
        float4 v = make_float4(0.f, 0.f, 0.f, 0.f);
        if (gr < N) v = Xg[(size_t)gr * 32 + c];
        uint16_t h0, l0, h1, l1, h2, l2, h3, l3;
        bsplit(v.x, h0, l0);
        bsplit(v.y, h1, l1);
        bsplit(v.z, h2, l2);
        bsplit(v.w, h3, l3);
        uint32_t* dst = As + r * AK + c * 6;
        ((uint2*)dst)[0] = make_uint2(pk(h0, l0), pk(h0, h1));
        ((uint2*)dst)[1] = make_uint2(pk(l1, h1), pk(h2, l2));
        ((uint2*)dst)[2] = make_uint2(pk(h2, h3), pk(l3, h3));
    }
}

__device__ __forceinline__ void fill_Bext(const uint32_t* __restrict__ Wext,
                                          uint32_t* Bs, int tid) {
    const uint4* src = (const uint4*)Wext;
#pragma unroll
    for (int i = tid; i < DMODEL * WWORDS / 4; i += 256) {
        int n = i / (WWORDS / 4);
        int w = i % (WWORDS / 4);
        *(uint4*)&Bs[n * AK + w * 4] = src[i];
    }
}

__device__ __forceinline__ void mm_mma(const uint32_t* As, const uint32_t* Bs,
                                       int mrow, int ncol, int g, int tig,
                                       float acc[2][8][4]) {
#pragma unroll
    for (int mi = 0; mi < 2; mi++)
#pragma unroll
        for (int ni = 0; ni < 8; ni++)
#pragma unroll
            for (int j = 0; j < 4; j++) acc[mi][ni][j] = 0.0f;

#pragma unroll 1
    for (int kc = 0; kc < 24; kc++) {
        int kw = kc * 8 + tig;
        uint32_t a[2][4];
#pragma unroll
        for (int mi = 0; mi < 2; mi++) {
            int r = mrow + mi * 16 + g;
            a[mi][0] = As[r * AK + kw];
            a[mi][1] = As[(r + 8) * AK + kw];
            a[mi][2] = As[r * AK + kw + 4];
            a[mi][3] = As[(r + 8) * AK + kw + 4];
        }
#pragma unroll
        for (int ni = 0; ni < 8; ni++) {
            int n = ncol + ni * 8 + g;
            uint32_t b0 = Bs[n * AK + kw];
            uint32_t b1 = Bs[n * AK + kw + 4];
            mma16816(acc[0][ni], a[0], b0, b1);
            mma16816(acc[1][ni], a[1], b0, b1);
        }
    }
}

// ---------------- merged fused Q/K/V projection (both node types, one launch) -----------
struct QkvArgs {
    const float* X[2];
    int N[2];
    int gb0;                     // blocks for node type 0
    const uint32_t* W[2][3];
    const float* b[2][3];
    float* Y[2][3];
    int ld[2][3];
    const float* prel[2];
};

__global__ __launch_bounds__(256) void gemm_qkv_all(QkvArgs qa) {
    extern __shared__ uint32_t smu[];
    uint32_t* As = smu;
    uint32_t* Bs = smu + DMODEL * AK;
    int tid = threadIdx.x;
    int t = (blockIdx.x < qa.gb0) ? 0 : 1;
    int row0 = (t == 0 ? blockIdx.x : blockIdx.x - qa.gb0) * DMODEL;
    int N = qa.N[t];
    int w = tid >> 5, lane = tid & 31;
    int g = lane >> 2, tig = lane & 3;
    int mrow = (w & 3) * 32;
    int ncol = (w >> 2) * 64;

    fill_Aext(qa.X[t], N, row0, As, tid);

#pragma unroll 1
    for (int m = 0; m < 3; m++) {
        fill_Bext(qa.W[t][m], Bs, tid);
        __syncthreads();

        float acc[2][8][4];
        mm_mma(As, Bs, mrow, ncol, g, tig, acc);

        const float* bias = qa.b[t][m];
        float* Y = qa.Y[t][m];
        int ld = qa.ld[t][m];
#pragma unroll
        for (int mi = 0; mi < 2; mi++) {
            int r0 = row0 + mrow + mi * 16 + g;
#pragma unroll
            for (int ni = 0; ni < 8; ni++) {
                int col = ncol + ni * 8 + 2 * tig;
                float sc = (m == 0) ? __ldg(&qa.prel[t][col >> 4]) * 0.25f : 1.0f;
                float bvx = bias[col], bvy = bias[col + 1];
                float* a4 = acc[mi][ni];
                if (r0 < N) {
                    float2 o;
                    o.x = (a4[0] + bvx) * sc;
                    o.y = (a4[1] + bvy) * sc;
                    *(float2*)&Y[(size_t)r0 * ld + col] = o;
                }
                if (r0 + 8 < N) {
                    float2 o;
                    o.x = (a4[2] + bvx) * sc;
                    o.y = (a4[3] + bvy) * sc;
                    *(float2*)&Y[(size_t)(r0 + 8) * ld + col] = o;
                }
            }
        }
        __syncthreads();
    }
}

// ---------------- merged output GEMM (both node types) ----------------
struct OutArgs {
    const float* Xagg[2];
    const uint32_t* W[2];
    const float* b[2];
    const float* skip[2];
    const float* Xres[2];
    float* Y[2];
    int N[2];
    int gb0;
};

__global__ __launch_bounds__(256) void gemm_out_all(OutArgs oa) {
    extern __shared__ uint32_t smu[];
    uint32_t* As = smu;
    uint32_t* Bs = smu + DMODEL * AK;
    int tid = threadIdx.x;
    int t = (blockIdx.x < oa.gb0) ? 0 : 1;
    int row0 = (t == 0 ? blockIdx.x : blockIdx.x - oa.gb0) * DMODEL;
    int N = oa.N[t];
    int w = tid >> 5, lane = tid & 31;
    int g = lane >> 2, tig = lane & 3;
    int mrow = (w & 3) * 32;
    int ncol = (w >> 2) * 64;

    fill_Aext(oa.Xagg[t], N, row0, As, tid);
    fill_Bext(oa.W[t], Bs, tid);
    __syncthreads();

    float acc[2][8][4];
    mm_mma(As, Bs, mrow, ncol, g, tig, acc);

    float al = 1.0f / (1.0f + __expf(-oa.skip[t][0]));
    float be = 1.0f - al;
    const float* bias = oa.b[t];
    const float* Xres = oa.Xres[t];
    float* Y = oa.Y[t];
#pragma unroll
    for (int mi = 0; mi < 2; mi++) {
        int r0 = row0 + mrow + mi * 16 + g;
#pragma unroll
        for (int ni = 0; ni < 8; ni++) {
            int col = ncol + ni * 8 + 2 * tig;
            float bvx = bias[col], bvy = bias[col + 1];
            float* a4 = acc[mi][ni];
            if (r0 < N) {
                float2 xr = *(const float2*)&Xres[(size_t)r0 * DMODEL + col];
                float2 o;
                o.x = al * (a4[0] + bvx) + be * xr.x;
                o.y = al * (a4[1] + bvy) + be * xr.y;
                *(float2*)&Y[(size_t)r0 * DMODEL + col] = o;
            }
            if (r0 + 8 < N) {
                float2 xr = *(const float2*)&Xres[(size_t)(r0 + 8) * DMODEL + col];
                float2 o;
                o.x = al * (a4[2] + bvx) + be * xr.x;
                o.y = al * (a4[3] + bvy) + be * xr.y;
                *(float2*)&Y[(size_t)(r0 + 8) * DMODEL + col] = o;
            }
        }
    }
}

// ---------------- merged per-dst attention, unrolled x2 for MLP ----------------
struct AttnArgs {
    const float* Q[2];
    const float* KV[2];
    const int* off[2];
    const int* esrc[2];
    float* agg[2];
    int N0;
};

__global__ void node_attn_all(AttnArgs aa) {
    int gg = blockIdx.x * blockDim.x + threadIdx.x;
    int w = gg >> 5;
    int lane = gg & 31;
    int t = (w < aa.N0) ? 0 : 1;
    if (t) w -= aa.N0;
    const float* Q = aa.Q[t];
    const float* KV = aa.KV[t];
    const int* esrc = aa.esrc[t];
    float4 q = ((const float4*)(Q + (size_t)w * DMODEL))[lane];
    int j0 = aa.off[t][w];
    int j1 = aa.off[t][w + 1];
    float4 acc = make_float4(0.f, 0.f, 0.f, 0.f);
    float den = 0.0f;
    int j = j0;
    for (; j + 1 < j1; j += 2) {
        int s0 = __ldg(&esrc[j]);
        int s1 = __ldg(&esrc[j + 1]);
        const float4* r0 = (const float4*)(KV + (size_t)s0 * KVLD);
        const float4* r1 = (const float4*)(KV + (size_t)s1 * KVLD);
        float4 k0 = __ldg(&r0[lane]);
        float4 k1 = __ldg(&r1[lane]);
        float4 v0 = __ldg(&r0[lane + 32]);
        float4 v1 = __ldg(&r1[lane + 32]);
        float p0 = k0.x * q.x + k0.y * q.y + k0.z * q.z + k0.w * q.w;
        float p1 = k1.x * q.x + k1.y * q.y + k1.z * q.z + k1.w * q.w;
        p0 += __shfl_xor_sync(0xffffffffu, p0, 1);
        p1 += __shfl_xor_sync(0xffffffffu, p1, 1);
        p0 += __shfl_xor_sync(0xffffffffu, p0, 2);
        p1 += __shfl_xor_sync(0xffffffffu, p1, 2);
        float e0 = __expf(p0);
        float e1 = __expf(p1);
        acc.x += e0 * v0.x + e1 * v1.x;
        acc.y += e0 * v0.y + e1 * v1.y;
        acc.z += e0 * v0.z + e1 * v1.z;
        acc.w += e0 * v0.w + e1 * v1.w;
        den += e0 + e1;
    }
    if (j < j1) {
        int s = __ldg(&esrc[j]);
        const float4* r0 = (const float4*)(KV + (size_t)s * KVLD);
        float4 k4 = __ldg(&r0[lane]);
        float4 v4 = __ldg(&r0[lane + 32]);
        float p = k4.x * q.x + k4.y * q.y + k4.z * q.z + k4.w * q.w;
        p += __shfl_xor_sync(0xffffffffu, p, 1);
        p += __shfl_xor_sync(0xffffffffu, p, 2);
        float ev = __expf(p);
        acc.x += ev * v4.x;
        acc.y += ev * v4.y;
        acc.z += ev * v4.z;
        acc.w += ev * v4.w;
        den += ev;
    }
    float inv = 1.0f / (den + 1e-16f);
    float4 o;
    o.x = acc.x * inv;
    o.y = acc.y * inv;
    o.z = acc.z * inv;
    o.w = acc.w * inv;
    ((float4*)(aa.agg[t] + (size_t)w * DMODEL))[lane] = o;
}

// ---------------- launch ----------------
extern "C" void kernel_launch(void* const* d_in, const int* in_sizes, int n_in,
                              void* d_out, int out_size) {
    const float* x_p = (const float*)d_in[0];
    const float* x_a = (const float*)d_in[1];
    const int* src_ap = (const int*)d_in[2];
    const int* dst_ap = (const int*)d_in[3];
    const int* src_pa = (const int*)d_in[4];
    const int* dst_pa = (const int*)d_in[5];
    const float* Wq_p = (const float*)d_in[6];
    const float* bq_p = (const float*)d_in[7];
    const float* Wk_p = (const float*)d_in[8];
    const float* bk_p = (const float*)d_in[9];
    const float* Wv_p = (const float*)d_in[10];
    const float* bv_p = (const float*)d_in[11];
    const float* Wa_p = (const float*)d_in[12];
    const float* ba_p = (const float*)d_in[13];
    const float* skip_p = (const float*)d_in[14];
    const float* Wq_a = (const float*)d_in[15];
    const float* bq_a = (const float*)d_in[16];
    const float* Wk_a = (const float*)d_in[17];
    const float* bk_a = (const float*)d_in[18];
    const float* Wv_a = (const float*)d_in[19];
    const float* bv_a = (const float*)d_in[20];
    const float* Wa_a = (const float*)d_in[21];
    const float* ba_a = (const float*)d_in[22];
    const float* skip_a = (const float*)d_in[23];
    const float* a_rel_ap = (const float*)d_in[24];
    const float* m_rel_ap = (const float*)d_in[25];
    const float* p_rel_ap = (const float*)d_in[26];
    const float* a_rel_pa = (const float*)d_in[27];
    const float* m_rel_pa = (const float*)d_in[28];
    const float* p_rel_pa = (const float*)d_in[29];
    float* out = (float*)d_out;

    int E_ap = in_sizes[2];
    int E_pa = in_sizes[4];

    float *Wk_ap, *Wv_ap, *Wk_pa, *Wv_pa, *bk_ap, *bv_ap, *bk_pa, *bv_pa;
    float *q_p, *q_a, *kv_ap, *kv_pa, *agg_p, *agg_a;
    uint32_t* wext;
    int *cnt_p, *cnt_a, *off_p, *off_a, *cur_p, *cur_a, *esrc_p, *esrc_a, *partials;
    cudaGetSymbolAddress((void**)&Wk_ap, g_Wk_ap);
    cudaGetSymbolAddress((void**)&Wv_ap, g_Wv_ap);
    cudaGetSymbolAddress((void**)&Wk_pa, g_Wk_pa);
    cudaGetSymbolAddress((void**)&Wv_pa, g_Wv_pa);
    cudaGetSymbolAddress((void**)&bk_ap, g_bk_ap);
    cudaGetSymbolAddress((void**)&bv_ap, g_bv_ap);
    cudaGetSymbolAddress((void**)&bk_pa, g_bk_pa);
    cudaGetSymbolAddress((void**)&bv_pa, g_bv_pa);
    cudaGetSymbolAddress((void**)&wext, g_wext);
    cudaGetSymbolAddress((void**)&q_p, g_q_p);
    cudaGetSymbolAddress((void**)&q_a, g_q_a);
    cudaGetSymbolAddress((void**)&kv_ap, g_kv_ap);
    cudaGetSymbolAddress((void**)&kv_pa, g_kv_pa);
    cudaGetSymbolAddress((void**)&agg_p, g_agg_p);
    cudaGetSymbolAddress((void**)&agg_a, g_agg_a);
    cudaGetSymbolAddress((void**)&cnt_p, g_cnt_p);
    cudaGetSymbolAddress((void**)&cnt_a, g_cnt_a);
    cudaGetSymbolAddress((void**)&off_p, g_off_p);
    cudaGetSymbolAddress((void**)&off_a, g_off_a);
    cudaGetSymbolAddress((void**)&cur_p, g_cur_p);
    cudaGetSymbolAddress((void**)&cur_a, g_cur_a);
    cudaGetSymbolAddress((void**)&esrc_p, g_esrc_p);
    cudaGetSymbolAddress((void**)&esrc_a, g_esrc_a);
    cudaGetSymbolAddress((void**)&partials, g_partials);

    const int SMEM = 2 * DMODEL * AK * (int)sizeof(uint32_t);  // 200704 B
    cudaFuncSetAttribute(gemm_qkv_all, cudaFuncAttributeMaxDynamicSharedMemorySize, SMEM);
    cudaFuncSetAttribute(gemm_out_all, cudaFuncAttributeMaxDynamicSharedMemorySize, SMEM);

    // launch 0: weight folding
    FuseArgs fa;
    fa.W[0] = Wk_a; fa.b[0] = bk_a; fa.rel[0] = a_rel_ap; fa.We[0] = Wk_ap; fa.be[0] = bk_ap;
    fa.W[1] = Wv_a; fa.b[1] = bv_a; fa.rel[1] = m_rel_ap; fa.We[1] = Wv_ap; fa.be[1] = bv_ap;
    fa.W[2] = Wk_p; fa.b[2] = bk_p; fa.rel[2] = a_rel_pa; fa.We[2] = Wk_pa; fa.be[2] = bk_pa;
    fa.W[3] = Wv_p; fa.b[3] = bv_p; fa.rel[3] = m_rel_pa; fa.We[3] = Wv_pa; fa.be[3] = bv_pa;
    fuse_all<<<dim3(DMODEL, 4), DMODEL>>>(fa);

    // launch 1: bf16-split all 8 weight matrices
    ConvArgs ca;
    ca.W[0] = Wq_p;  ca.W[1] = Wk_pa; ca.W[2] = Wv_pa;
    ca.W[3] = Wq_a;  ca.W[4] = Wk_ap; ca.W[5] = Wv_ap;
    ca.W[6] = Wa_p;  ca.W[7] = Wa_a;
    convert_w<<<dim3(DMODEL, 8), 64>>>(ca);

    // launch 2: zero histogram counters
    fill_cnt<<<256, 256>>>(cnt_p, NP, cnt_a, NA);

    // launch 3 (ncu window): merged QKV projections for both node types
    int gb_p = (NP + DMODEL - 1) / DMODEL;
    int gb_a = (NA + DMODEL - 1) / DMODEL;
    QkvArgs qa;
    qa.X[0] = x_p;  qa.N[0] = NP;
    qa.X[1] = x_a;  qa.N[1] = NA;
    qa.gb0 = gb_p;
    qa.W[0][0] = wext + 0 * DMODEL * WWORDS; qa.b[0][0] = bq_p;  qa.Y[0][0] = q_p;           qa.ld[0][0] = DMODEL;
    qa.W[0][1] = wext + 1 * DMODEL * WWORDS; qa.b[0][1] = bk_pa; qa.Y[0][1] = kv_pa;         qa.ld[0][1] = KVLD;
    qa.W[0][2] = wext + 2 * DMODEL * WWORDS; qa.b[0][2] = bv_pa; qa.Y[0][2] = kv_pa + DMODEL; qa.ld[0][2] = KVLD;
    qa.W[1][0] = wext + 3 * DMODEL * WWORDS; qa.b[1][0] = bq_a;  qa.Y[1][0] = q_a;           qa.ld[1][0] = DMODEL;
    qa.W[1][1] = wext + 4 * DMODEL * WWORDS; qa.b[1][1] = bk_ap; qa.Y[1][1] = kv_ap;         qa.ld[1][1] = KVLD;
    qa.W[1][2] = wext + 5 * DMODEL * WWORDS; qa.b[1][2] = bv_ap; qa.Y[1][2] = kv_ap + DMODEL; qa.ld[1][2] = KVLD;
    qa.prel[0] = p_rel_ap;
    qa.prel[1] = p_rel_pa;
    gemm_qkv_all<<<gb_p + gb_a, 256, SMEM>>>(qa);

    // launches 4-7: CSR build
    hist2<<<2048, 256>>>(dst_ap, E_ap, cnt_p, dst_pa, E_pa, cnt_a);
    scan_local<<<NBP + NBA, 1024>>>(cnt_p, cnt_a, off_p, off_a, partials);
    scan_partials<<<1, 32>>>(partials, off_p, off_a);
    add_base<<<NBP + NBA, 1024>>>(off_p, off_a, cur_p, cur_a, partials);
    build_esrc<<<2048, 256>>>(src_ap, dst_ap, E_ap, cur_p, esrc_p,
                              src_pa, dst_pa, E_pa, cur_a, esrc_a);

    // launch 8: merged fused attention (both node types)
    AttnArgs aa;
    aa.Q[0] = q_p;  aa.KV[0] = kv_ap; aa.off[0] = off_p; aa.esrc[0] = esrc_p; aa.agg[0] = agg_p;
    aa.Q[1] = q_a;  aa.KV[1] = kv_pa; aa.off[1] = off_a; aa.esrc[1] = esrc_a; aa.agg[1] = agg_a;
    aa.N0 = NP;
    node_attn_all<<<((NP + NA) * 32 + 255) / 256, 256>>>(aa);

    // launch 9: merged output projections + skip blend
    OutArgs oa;
    oa.Xagg[0] = agg_p; oa.W[0] = wext + 6 * DMODEL * WWORDS; oa.b[0] = ba_p;
    oa.skip[0] = skip_p; oa.Xres[0] = x_p; oa.Y[0] = out; oa.N[0] = NP;
    oa.Xagg[1] = agg_a; oa.W[1] = wext + 7 * DMODEL * WWORDS; oa.b[1] = ba_a;
    oa.skip[1] = skip_a; oa.Xres[1] = x_a; oa.Y[1] = out + (size_t)NP * DMODEL; oa.N[1] = NA;
    oa.gb0 = gb_p;
    gemm_out_all<<<gb_p + gb_a, 256, SMEM>>>(oa);
}